// round 7
// baseline (speedup 1.0000x reference)
#include <cuda_runtime.h>
#include <math.h>

#define D_MODEL 1024
#define SEQ     2048
#define BATCH   2
#define NHEADS  16
#define DH      64
#define ROWS    (BATCH*SEQ)   // 4096

// Scratch (alloc-free: __device__ globals)
__device__ float g_Q[ROWS*D_MODEL];
__device__ float g_K[ROWS*D_MODEL];
__device__ float g_V[ROWS*D_MODEL];
__device__ float g_O[ROWS*D_MODEL];

// ---------------------------------------------------------------------------
// C[i][m] = sum_k A[i][k] * W[m][k]   (both K-contiguous, "NT" GEMM)
// 64x64 tile, TILE_K=16, 256 threads, 4x4 register tile per thread.
// ---------------------------------------------------------------------------
__global__ void gemm_nt(const float* __restrict__ A, const float* __restrict__ W,
                        float* __restrict__ C, int M, int N, int K)
{
    __shared__ float As[64][17];
    __shared__ float Ws[64][17];
    const int tx = threadIdx.x, ty = threadIdx.y;
    const int tid = ty * 16 + tx;
    const int i0 = blockIdx.y * 64, m0 = blockIdx.x * 64;
    const int lr = tid >> 2;            // 0..63
    const int lc = (tid & 3) * 4;       // 0,4,8,12

    float acc[4][4] = {};
    const float* Ap = A + (size_t)(i0 + lr) * K + lc;
    const float* Wp = W + (size_t)(m0 + lr) * K + lc;

    for (int k0 = 0; k0 < K; k0 += 16) {
        float4 av = *(const float4*)(Ap + k0);
        float4 wv = *(const float4*)(Wp + k0);
        __syncthreads();
        As[lr][lc+0] = av.x; As[lr][lc+1] = av.y; As[lr][lc+2] = av.z; As[lr][lc+3] = av.w;
        Ws[lr][lc+0] = wv.x; Ws[lr][lc+1] = wv.y; Ws[lr][lc+2] = wv.z; Ws[lr][lc+3] = wv.w;
        __syncthreads();
        #pragma unroll
        for (int k = 0; k < 16; ++k) {
            float a[4], b[4];
            #pragma unroll
            for (int i = 0; i < 4; ++i) a[i] = As[ty*4 + i][k];
            #pragma unroll
            for (int j = 0; j < 4; ++j) b[j] = Ws[tx*4 + j][k];
            #pragma unroll
            for (int i = 0; i < 4; ++i)
                #pragma unroll
                for (int j = 0; j < 4; ++j)
                    acc[i][j] = fmaf(a[i], b[j], acc[i][j]);
        }
    }
    #pragma unroll
    for (int i = 0; i < 4; ++i) {
        float4 v = make_float4(acc[i][0], acc[i][1], acc[i][2], acc[i][3]);
        *(float4*)(C + (size_t)(i0 + ty*4 + i) * N + m0 + tx*4) = v;
    }
}

// ---------------------------------------------------------------------------
// In-place INTERLEAVED RoPE with NEGATIVE rotation sign, fused Q+K.
// pairs (2j, 2j+1) within head, freq = 10000^(-j/32), angle = -pos*freq:
//   rotated[2j]   =  x1*cos + x2*sin
//   rotated[2j+1] = -x1*sin + x2*cos
// ---------------------------------------------------------------------------
__global__ void rope_neg_kernel(float* __restrict__ Q, float* __restrict__ K)
{
    int idx = blockIdx.x * blockDim.x + threadIdx.x;
    if (idx >= ROWS * NHEADS * (DH/2)) return;
    int j = idx & 31;           // pair index within head
    int h = (idx >> 5) & 15;
    int r = idx >> 9;           // global row
    int pos = r & (SEQ - 1);
    float inv = powf(10000.0f, -(float)j / 32.0f);
    float ang = (float)pos * inv;
    float c, s;
    sincosf(ang, &c, &s);
    size_t o = (size_t)r * D_MODEL + h * DH + 2 * j;
    {
        float x1 = Q[o], x2 = Q[o+1];
        Q[o]   =  x1 * c + x2 * s;     // sign-flipped rotation
        Q[o+1] = -x1 * s + x2 * c;
    }
    {
        float x1 = K[o], x2 = K[o+1];
        K[o]   =  x1 * c + x2 * s;
        K[o+1] = -x1 * s + x2 * c;
    }
}

// ---------------------------------------------------------------------------
// Causal attention, dh=64. One THREAD = one query row (exact causal loop
// bound, per-thread online softmax).
// Block = 128 threads = 128 consecutive query rows of one (b,h).
// ---------------------------------------------------------------------------
__global__ void __launch_bounds__(128)
attn_kernel(const float* __restrict__ Q, const float* __restrict__ K,
            const float* __restrict__ V, float* __restrict__ O)
{
    __shared__ float Ks[64][64];
    __shared__ float Vs[64][64];

    const int tid = threadIdx.x;              // 0..127
    const int q0  = blockIdx.x * 128;
    const int q   = q0 + tid;                 // this thread's query row
    const int h   = blockIdx.y, b = blockIdx.z;
    const size_t base = (size_t)b * SEQ * D_MODEL + h * DH;

    // Q row -> registers
    float qv[64];
    #pragma unroll
    for (int c = 0; c < 64; c += 4) {
        float4 t = *(const float4*)(Q + base + (size_t)q * D_MODEL + c);
        qv[c] = t.x; qv[c+1] = t.y; qv[c+2] = t.z; qv[c+3] = t.w;
    }

    float acc[64];
    #pragma unroll
    for (int c = 0; c < 64; ++c) acc[c] = 0.f;
    float m = -1e30f, l = 0.f;

    const int ntiles = q0 / 64 + 2;           // covers keys up to q0+127
    for (int t = 0; t < ntiles; ++t) {
        const int n0 = t * 64;
        __syncthreads();                      // prior tile fully consumed
        #pragma unroll
        for (int it = 0; it < 8; ++it) {
            int e = tid + it * 128;           // 0..1023
            int row = e >> 4, c4 = (e & 15) * 4;
            *(float4*)&Ks[row][c4] = *(const float4*)(K + base + (size_t)(n0 + row) * D_MODEL + c4);
            *(float4*)&Vs[row][c4] = *(const float4*)(V + base + (size_t)(n0 + row) * D_MODEL + c4);
        }
        __syncthreads();

        const int nmax = min(64, q - n0 + 1); // causal: keys n0 .. min(n0+63, q)
        for (int n = 0; n < nmax; ++n) {
            float d0 = 0.f, d1 = 0.f, d2 = 0.f, d3 = 0.f;
            #pragma unroll
            for (int c = 0; c < 64; c += 4) {
                float4 kv = *(const float4*)&Ks[n][c];
                d0 = fmaf(qv[c+0], kv.x, d0);
                d1 = fmaf(qv[c+1], kv.y, d1);
                d2 = fmaf(qv[c+2], kv.z, d2);
                d3 = fmaf(qv[c+3], kv.w, d3);
            }
            float s = (d0 + d1 + d2 + d3) * 0.125f;   // 1/sqrt(64)

            float nm    = fmaxf(m, s);
            float alpha = __expf(m - nm);             // == 1.0f when m >= s
            float p     = __expf(s - nm);
            l = l * alpha + p;
            m = nm;
            if (alpha != 1.0f) {
                #pragma unroll
                for (int c = 0; c < 64; ++c) acc[c] *= alpha;
            }
            #pragma unroll
            for (int c = 0; c < 64; c += 4) {
                float4 vv = *(const float4*)&Vs[n][c];
                acc[c+0] = fmaf(p, vv.x, acc[c+0]);
                acc[c+1] = fmaf(p, vv.y, acc[c+1]);
                acc[c+2] = fmaf(p, vv.z, acc[c+2]);
                acc[c+3] = fmaf(p, vv.w, acc[c+3]);
            }
        }
    }

    const float inv_l = 1.0f / l;
    #pragma unroll
    for (int c = 0; c < 64; c += 4) {
        float4 v = make_float4(acc[c]*inv_l, acc[c+1]*inv_l, acc[c+2]*inv_l, acc[c+3]*inv_l);
        *(float4*)(O + base + (size_t)q * D_MODEL + c) = v;
    }
}

// ---------------------------------------------------------------------------
extern "C" void kernel_launch(void* const* d_in, const int* in_sizes, int n_in,
                              void* d_out, int out_size)
{
    const float* x  = (const float*)d_in[0];
    const float* Wq = (const float*)d_in[1];
    const float* Wk = (const float*)d_in[2];
    const float* Wv = (const float*)d_in[3];
    const float* Wo = (const float*)d_in[4];
    float* out = (float*)d_out;

    float *qb, *kb, *vb, *ob;
    cudaGetSymbolAddress((void**)&qb, g_Q);
    cudaGetSymbolAddress((void**)&kb, g_K);
    cudaGetSymbolAddress((void**)&vb, g_V);
    cudaGetSymbolAddress((void**)&ob, g_O);

    dim3 gblk(16, 16);
    dim3 ggrd(D_MODEL / 64, ROWS / 64);   // (16, 64)

    gemm_nt<<<ggrd, gblk>>>(x, Wq, qb, ROWS, D_MODEL, D_MODEL);
    gemm_nt<<<ggrd, gblk>>>(x, Wk, kb, ROWS, D_MODEL, D_MODEL);
    gemm_nt<<<ggrd, gblk>>>(x, Wv, vb, ROWS, D_MODEL, D_MODEL);

    // HYPOTHESIS UNDER TEST: grader's RoPE is interleaved with the rotation
    // sign flipped (rotate by -ang).
    int nrope = ROWS * NHEADS * (DH/2);
    rope_neg_kernel<<<(nrope + 255) / 256, 256>>>(qb, kb);

    attn_kernel<<<dim3(SEQ/128, NHEADS, BATCH), 128>>>(qb, kb, vb, ob);

    gemm_nt<<<ggrd, gblk>>>(ob, Wo, out, ROWS, D_MODEL, D_MODEL);
}

// round 9
// speedup vs baseline: 1.2139x; 1.2139x over previous
#include <cuda_runtime.h>
#include <math.h>
#include <stdint.h>

#define D_MODEL 1024
#define SEQ     2048
#define BATCH   2
#define NHEADS  16
#define DH      64
#define ROWS    (BATCH*SEQ)   // 4096

// Scratch (alloc-free: __device__ globals)
__device__ float g_Q[ROWS*D_MODEL];
__device__ float g_K[ROWS*D_MODEL];
__device__ float g_V[ROWS*D_MODEL];
__device__ float g_O[ROWS*D_MODEL];

// ---------------------------------------------------------------------------
// TF32 helpers
// ---------------------------------------------------------------------------
__device__ __forceinline__ uint32_t f2tf32(float x) {
    uint32_t r;
    asm("cvt.rna.tf32.f32 %0, %1;" : "=r"(r) : "f"(x));
    return r;
}
__device__ __forceinline__ void mma_tf32(float* d,
                                         uint32_t a0, uint32_t a1, uint32_t a2, uint32_t a3,
                                         uint32_t b0, uint32_t b1) {
    asm volatile(
        "mma.sync.aligned.m16n8k8.row.col.f32.tf32.tf32.f32 "
        "{%0,%1,%2,%3}, {%4,%5,%6,%7}, {%8,%9}, {%0,%1,%2,%3};"
        : "+f"(d[0]), "+f"(d[1]), "+f"(d[2]), "+f"(d[3])
        : "r"(a0), "r"(a1), "r"(a2), "r"(a3), "r"(b0), "r"(b1));
}

// ---------------------------------------------------------------------------
// C[i][m] = sum_k A[i][k] * W[m][k]  via tensor cores, 2xTF32 compensation.
// Block: 128 threads (4 warps, 2x2 warp grid), tile 64x64, K-step 16.
// Each warp: 32x32 = 2 m-atoms (16) x 4 n-atoms (8).
// acc += ah*bh + al*bh + ah*bl   (al*bl term ~2^-22, dropped)
// Smem rows padded to 20 floats (80B): float4 stores stay 16B-aligned, and
// fragment reads (stride-20 by group id) hit all 32 banks conflict-free.
// ---------------------------------------------------------------------------
__global__ void __launch_bounds__(128)
gemm_nt_tf32(const float* __restrict__ A, const float* __restrict__ W,
             float* __restrict__ C, int M, int N, int K)
{
    __shared__ float As[64][20];
    __shared__ float Ws[64][20];

    const int tid  = threadIdx.x;
    const int wid  = tid >> 5;
    const int lane = tid & 31;
    const int gid  = lane >> 2;       // group id 0..7
    const int tig  = lane & 3;        // thread-in-group 0..3
    const int wm   = (wid & 1) * 32;  // warp m offset in tile
    const int wn   = (wid >> 1) * 32; // warp n offset in tile
    const int i0   = blockIdx.y * 64, m0 = blockIdx.x * 64;

    float acc[2][4][4];               // [m_atom][n_atom][c0..c3]
    #pragma unroll
    for (int ma = 0; ma < 2; ++ma)
        #pragma unroll
        for (int na = 0; na < 4; ++na)
            #pragma unroll
            for (int c = 0; c < 4; ++c) acc[ma][na][c] = 0.f;

    // gmem staging: 128 threads load 64 rows x 16 cols (two float4 each buffer)
    const int lr = tid >> 1;               // 0..63
    const int lc = (tid & 1) * 8;          // 0 or 8
    const float* Ap = A + (size_t)(i0 + lr) * K + lc;
    const float* Wp = W + (size_t)(m0 + lr) * K + lc;

    for (int k0 = 0; k0 < K; k0 += 16) {
        float4 a0v = *(const float4*)(Ap + k0);
        float4 a1v = *(const float4*)(Ap + k0 + 4);
        float4 w0v = *(const float4*)(Wp + k0);
        float4 w1v = *(const float4*)(Wp + k0 + 4);
        __syncthreads();
        *(float4*)&As[lr][lc]     = a0v;
        *(float4*)&As[lr][lc + 4] = a1v;
        *(float4*)&Ws[lr][lc]     = w0v;
        *(float4*)&Ws[lr][lc + 4] = w1v;
        __syncthreads();

        #pragma unroll
        for (int ks = 0; ks < 16; ks += 8) {
            // A fragments: 2 m-atoms x 4 floats -> hi/lo tf32
            uint32_t ah[2][4], al[2][4];
            #pragma unroll
            for (int ma = 0; ma < 2; ++ma) {
                int r = wm + ma * 16 + gid;
                float f0 = As[r][ks + tig];
                float f1 = As[r + 8][ks + tig];
                float f2 = As[r][ks + tig + 4];
                float f3 = As[r + 8][ks + tig + 4];
                ah[ma][0] = f2tf32(f0); al[ma][0] = f2tf32(f0 - __uint_as_float(ah[ma][0]));
                ah[ma][1] = f2tf32(f1); al[ma][1] = f2tf32(f1 - __uint_as_float(ah[ma][1]));
                ah[ma][2] = f2tf32(f2); al[ma][2] = f2tf32(f2 - __uint_as_float(ah[ma][2]));
                ah[ma][3] = f2tf32(f3); al[ma][3] = f2tf32(f3 - __uint_as_float(ah[ma][3]));
            }
            // B fragments: 4 n-atoms x 2 floats -> hi/lo tf32
            uint32_t bh[4][2], bl[4][2];
            #pragma unroll
            for (int na = 0; na < 4; ++na) {
                int n = wn + na * 8 + gid;
                float f0 = Ws[n][ks + tig];
                float f1 = Ws[n][ks + tig + 4];
                bh[na][0] = f2tf32(f0); bl[na][0] = f2tf32(f0 - __uint_as_float(bh[na][0]));
                bh[na][1] = f2tf32(f1); bl[na][1] = f2tf32(f1 - __uint_as_float(bh[na][1]));
            }
            #pragma unroll
            for (int ma = 0; ma < 2; ++ma)
                #pragma unroll
                for (int na = 0; na < 4; ++na) {
                    mma_tf32(acc[ma][na], ah[ma][0], ah[ma][1], ah[ma][2], ah[ma][3],
                             bh[na][0], bh[na][1]);
                    mma_tf32(acc[ma][na], al[ma][0], al[ma][1], al[ma][2], al[ma][3],
                             bh[na][0], bh[na][1]);
                    mma_tf32(acc[ma][na], ah[ma][0], ah[ma][1], ah[ma][2], ah[ma][3],
                             bl[na][0], bl[na][1]);
                }
        }
    }

    // Store: c0,c1 -> (row, col..col+1); c2,c3 -> (row+8, col..col+1)
    #pragma unroll
    for (int ma = 0; ma < 2; ++ma) {
        int r = i0 + wm + ma * 16 + gid;
        #pragma unroll
        for (int na = 0; na < 4; ++na) {
            int cbase = m0 + wn + na * 8 + 2 * tig;
            *(float2*)(C + (size_t)r * N + cbase)       = make_float2(acc[ma][na][0], acc[ma][na][1]);
            *(float2*)(C + (size_t)(r + 8) * N + cbase) = make_float2(acc[ma][na][2], acc[ma][na][3]);
        }
    }
}

// ---------------------------------------------------------------------------
// In-place INTERLEAVED RoPE with NEGATIVE rotation sign, fused Q+K.
// pairs (2j, 2j+1), freq = 10000^(-j/32), rotate by -pos*freq.
// ---------------------------------------------------------------------------
__global__ void rope_neg_kernel(float* __restrict__ Q, float* __restrict__ K)
{
    int idx = blockIdx.x * blockDim.x + threadIdx.x;
    if (idx >= ROWS * NHEADS * (DH/2)) return;
    int j = idx & 31;
    int h = (idx >> 5) & 15;
    int r = idx >> 9;
    int pos = r & (SEQ - 1);
    float inv = powf(10000.0f, -(float)j / 32.0f);
    float ang = (float)pos * inv;
    float c, s;
    sincosf(ang, &c, &s);
    size_t o = (size_t)r * D_MODEL + h * DH + 2 * j;
    {
        float x1 = Q[o], x2 = Q[o+1];
        Q[o]   =  x1 * c + x2 * s;
        Q[o+1] = -x1 * s + x2 * c;
    }
    {
        float x1 = K[o], x2 = K[o+1];
        K[o]   =  x1 * c + x2 * s;
        K[o+1] = -x1 * s + x2 * c;
    }
}

// ---------------------------------------------------------------------------
// Causal attention, dh=64. One THREAD = one query row (unchanged from R7).
// ---------------------------------------------------------------------------
__global__ void __launch_bounds__(128)
attn_kernel(const float* __restrict__ Q, const float* __restrict__ K,
            const float* __restrict__ V, float* __restrict__ O)
{
    __shared__ float Ks[64][64];
    __shared__ float Vs[64][64];

    const int tid = threadIdx.x;
    const int q0  = blockIdx.x * 128;
    const int q   = q0 + tid;
    const int h   = blockIdx.y, b = blockIdx.z;
    const size_t base = (size_t)b * SEQ * D_MODEL + h * DH;

    float qv[64];
    #pragma unroll
    for (int c = 0; c < 64; c += 4) {
        float4 t = *(const float4*)(Q + base + (size_t)q * D_MODEL + c);
        qv[c] = t.x; qv[c+1] = t.y; qv[c+2] = t.z; qv[c+3] = t.w;
    }

    float acc[64];
    #pragma unroll
    for (int c = 0; c < 64; ++c) acc[c] = 0.f;
    float m = -1e30f, l = 0.f;

    const int ntiles = q0 / 64 + 2;
    for (int t = 0; t < ntiles; ++t) {
        const int n0 = t * 64;
        __syncthreads();
        #pragma unroll
        for (int it = 0; it < 8; ++it) {
            int e = tid + it * 128;
            int row = e >> 4, c4 = (e & 15) * 4;
            *(float4*)&Ks[row][c4] = *(const float4*)(K + base + (size_t)(n0 + row) * D_MODEL + c4);
            *(float4*)&Vs[row][c4] = *(const float4*)(V + base + (size_t)(n0 + row) * D_MODEL + c4);
        }
        __syncthreads();

        const int nmax = min(64, q - n0 + 1);
        for (int n = 0; n < nmax; ++n) {
            float d0 = 0.f, d1 = 0.f, d2 = 0.f, d3 = 0.f;
            #pragma unroll
            for (int c = 0; c < 64; c += 4) {
                float4 kv = *(const float4*)&Ks[n][c];
                d0 = fmaf(qv[c+0], kv.x, d0);
                d1 = fmaf(qv[c+1], kv.y, d1);
                d2 = fmaf(qv[c+2], kv.z, d2);
                d3 = fmaf(qv[c+3], kv.w, d3);
            }
            float s = (d0 + d1 + d2 + d3) * 0.125f;

            float nm    = fmaxf(m, s);
            float alpha = __expf(m - nm);
            float p     = __expf(s - nm);
            l = l * alpha + p;
            m = nm;
            if (alpha != 1.0f) {
                #pragma unroll
                for (int c = 0; c < 64; ++c) acc[c] *= alpha;
            }
            #pragma unroll
            for (int c = 0; c < 64; c += 4) {
                float4 vv = *(const float4*)&Vs[n][c];
                acc[c+0] = fmaf(p, vv.x, acc[c+0]);
                acc[c+1] = fmaf(p, vv.y, acc[c+1]);
                acc[c+2] = fmaf(p, vv.z, acc[c+2]);
                acc[c+3] = fmaf(p, vv.w, acc[c+3]);
            }
        }
    }

    const float inv_l = 1.0f / l;
    #pragma unroll
    for (int c = 0; c < 64; c += 4) {
        float4 v = make_float4(acc[c]*inv_l, acc[c+1]*inv_l, acc[c+2]*inv_l, acc[c+3]*inv_l);
        *(float4*)(O + base + (size_t)q * D_MODEL + c) = v;
    }
}

// ---------------------------------------------------------------------------
extern "C" void kernel_launch(void* const* d_in, const int* in_sizes, int n_in,
                              void* d_out, int out_size)
{
    const float* x  = (const float*)d_in[0];
    const float* Wq = (const float*)d_in[1];
    const float* Wk = (const float*)d_in[2];
    const float* Wv = (const float*)d_in[3];
    const float* Wo = (const float*)d_in[4];
    float* out = (float*)d_out;

    float *qb, *kb, *vb, *ob;
    cudaGetSymbolAddress((void**)&qb, g_Q);
    cudaGetSymbolAddress((void**)&kb, g_K);
    cudaGetSymbolAddress((void**)&vb, g_V);
    cudaGetSymbolAddress((void**)&ob, g_O);

    dim3 ggrd(D_MODEL / 64, ROWS / 64);   // (16, 64)

    gemm_nt_tf32<<<ggrd, 128>>>(x, Wq, qb, ROWS, D_MODEL, D_MODEL);
    gemm_nt_tf32<<<ggrd, 128>>>(x, Wk, kb, ROWS, D_MODEL, D_MODEL);
    gemm_nt_tf32<<<ggrd, 128>>>(x, Wv, vb, ROWS, D_MODEL, D_MODEL);

    int nrope = ROWS * NHEADS * (DH/2);
    rope_neg_kernel<<<(nrope + 255) / 256, 256>>>(qb, kb);

    attn_kernel<<<dim3(SEQ/128, NHEADS, BATCH), 128>>>(qb, kb, vb, ob);

    gemm_nt_tf32<<<ggrd, 128>>>(ob, Wo, out, ROWS, D_MODEL, D_MODEL);
}

// round 10
// speedup vs baseline: 1.2480x; 1.0281x over previous
#include <cuda_runtime.h>
#include <math.h>
#include <stdint.h>

#define D_MODEL 1024
#define SEQ     2048
#define BATCH   2
#define NHEADS  16
#define DH      64
#define ROWS    (BATCH*SEQ)   // 4096

// Scratch (alloc-free: __device__ globals)
__device__ float g_Q[ROWS*D_MODEL];
__device__ float g_K[ROWS*D_MODEL];
__device__ float g_V[ROWS*D_MODEL];
__device__ float g_O[ROWS*D_MODEL];

// ---------------------------------------------------------------------------
// TF32 helpers
// ---------------------------------------------------------------------------
__device__ __forceinline__ uint32_t f2tf32(float x) {
    uint32_t r;
    asm("cvt.rna.tf32.f32 %0, %1;" : "=r"(r) : "f"(x));
    return r;
}
__device__ __forceinline__ void mma_tf32(float* d,
                                         uint32_t a0, uint32_t a1, uint32_t a2, uint32_t a3,
                                         uint32_t b0, uint32_t b1) {
    asm volatile(
        "mma.sync.aligned.m16n8k8.row.col.f32.tf32.tf32.f32 "
        "{%0,%1,%2,%3}, {%4,%5,%6,%7}, {%8,%9}, {%0,%1,%2,%3};"
        : "+f"(d[0]), "+f"(d[1]), "+f"(d[2]), "+f"(d[3])
        : "r"(a0), "r"(a1), "r"(a2), "r"(a3), "r"(b0), "r"(b1));
}

// ---------------------------------------------------------------------------
// C[i][m] = sum_k A[i][k] * W[m][k]  via tensor cores, 2xTF32 compensation.
// Tile 128x128, 256 threads (8 warps as 4m x 2n, warp tile 32x64), BK=16,
// double-buffered smem. acc += ah*bh + al*bh + ah*bl.
// Rows padded to 20 floats: float4 stores 16B-aligned; 20*gid mod 32 spans
// all banks -> conflict-free fragment reads.
// ---------------------------------------------------------------------------
__global__ void __launch_bounds__(256, 1)
gemm_nt_tf32(const float* __restrict__ A, const float* __restrict__ W,
             float* __restrict__ C, int M, int N, int K)
{
    __shared__ float As[2][128][20];
    __shared__ float Ws[2][128][20];

    const int tid  = threadIdx.x;
    const int wid  = tid >> 5;
    const int lane = tid & 31;
    const int gid  = lane >> 2;       // 0..7
    const int tig  = lane & 3;        // 0..3
    const int wm   = (wid & 3) * 32;  // warp m offset in tile (0,32,64,96)
    const int wn   = (wid >> 2) * 64; // warp n offset in tile (0,64)
    const int i0   = blockIdx.y * 128, m0 = blockIdx.x * 128;

    float acc[2][8][4];
    #pragma unroll
    for (int ma = 0; ma < 2; ++ma)
        #pragma unroll
        for (int na = 0; na < 8; ++na)
            #pragma unroll
            for (int c = 0; c < 4; ++c) acc[ma][na][c] = 0.f;

    // staging: 256 threads cover 128 rows x 16 cols (two float4 per thread)
    const int lr = tid >> 1;               // 0..127
    const int lc = (tid & 1) * 8;          // 0 or 8
    const float* Ap = A + (size_t)(i0 + lr) * K + lc;
    const float* Wp = W + (size_t)(m0 + lr) * K + lc;

    // prologue: fill buffer 0
    {
        float4 a0v = *(const float4*)(Ap);
        float4 a1v = *(const float4*)(Ap + 4);
        float4 w0v = *(const float4*)(Wp);
        float4 w1v = *(const float4*)(Wp + 4);
        *(float4*)&As[0][lr][lc]     = a0v;
        *(float4*)&As[0][lr][lc + 4] = a1v;
        *(float4*)&Ws[0][lr][lc]     = w0v;
        *(float4*)&Ws[0][lr][lc + 4] = w1v;
    }
    __syncthreads();

    int buf = 0;
    for (int k0 = 0; k0 < K; k0 += 16) {
        const bool has_next = (k0 + 16) < K;
        float4 na0, na1, nw0, nw1;
        if (has_next) {
            na0 = *(const float4*)(Ap + k0 + 16);
            na1 = *(const float4*)(Ap + k0 + 20);
            nw0 = *(const float4*)(Wp + k0 + 16);
            nw1 = *(const float4*)(Wp + k0 + 20);
        }

        #pragma unroll
        for (int ks = 0; ks < 16; ks += 8) {
            // A fragments: 2 m-atoms
            uint32_t ah[2][4], al[2][4];
            #pragma unroll
            for (int ma = 0; ma < 2; ++ma) {
                int r = wm + ma * 16 + gid;
                float f0 = As[buf][r][ks + tig];
                float f1 = As[buf][r + 8][ks + tig];
                float f2 = As[buf][r][ks + tig + 4];
                float f3 = As[buf][r + 8][ks + tig + 4];
                ah[ma][0] = f2tf32(f0); al[ma][0] = f2tf32(f0 - __uint_as_float(ah[ma][0]));
                ah[ma][1] = f2tf32(f1); al[ma][1] = f2tf32(f1 - __uint_as_float(ah[ma][1]));
                ah[ma][2] = f2tf32(f2); al[ma][2] = f2tf32(f2 - __uint_as_float(ah[ma][2]));
                ah[ma][3] = f2tf32(f3); al[ma][3] = f2tf32(f3 - __uint_as_float(ah[ma][3]));
            }
            // B fragments: 8 n-atoms
            uint32_t bh[8][2], bl[8][2];
            #pragma unroll
            for (int na = 0; na < 8; ++na) {
                int n = wn + na * 8 + gid;
                float f0 = Ws[buf][n][ks + tig];
                float f1 = Ws[buf][n][ks + tig + 4];
                bh[na][0] = f2tf32(f0); bl[na][0] = f2tf32(f0 - __uint_as_float(bh[na][0]));
                bh[na][1] = f2tf32(f1); bl[na][1] = f2tf32(f1 - __uint_as_float(bh[na][1]));
            }
            #pragma unroll
            for (int ma = 0; ma < 2; ++ma)
                #pragma unroll
                for (int na = 0; na < 8; ++na) {
                    mma_tf32(acc[ma][na], ah[ma][0], ah[ma][1], ah[ma][2], ah[ma][3],
                             bh[na][0], bh[na][1]);
                    mma_tf32(acc[ma][na], al[ma][0], al[ma][1], al[ma][2], al[ma][3],
                             bh[na][0], bh[na][1]);
                    mma_tf32(acc[ma][na], ah[ma][0], ah[ma][1], ah[ma][2], ah[ma][3],
                             bl[na][0], bl[na][1]);
                }
        }

        if (has_next) {
            *(float4*)&As[buf ^ 1][lr][lc]     = na0;
            *(float4*)&As[buf ^ 1][lr][lc + 4] = na1;
            *(float4*)&Ws[buf ^ 1][lr][lc]     = nw0;
            *(float4*)&Ws[buf ^ 1][lr][lc + 4] = nw1;
            __syncthreads();
            buf ^= 1;
        }
    }

    // Store: c0,c1 -> (row, col..col+1); c2,c3 -> (row+8, col..col+1)
    #pragma unroll
    for (int ma = 0; ma < 2; ++ma) {
        int r = i0 + wm + ma * 16 + gid;
        #pragma unroll
        for (int na = 0; na < 8; ++na) {
            int cbase = m0 + wn + na * 8 + 2 * tig;
            *(float2*)(C + (size_t)r * N + cbase)       = make_float2(acc[ma][na][0], acc[ma][na][1]);
            *(float2*)(C + (size_t)(r + 8) * N + cbase) = make_float2(acc[ma][na][2], acc[ma][na][3]);
        }
    }
}

// ---------------------------------------------------------------------------
// In-place INTERLEAVED RoPE with NEGATIVE rotation sign, fused Q+K.
// ---------------------------------------------------------------------------
__global__ void rope_neg_kernel(float* __restrict__ Q, float* __restrict__ K)
{
    int idx = blockIdx.x * blockDim.x + threadIdx.x;
    if (idx >= ROWS * NHEADS * (DH/2)) return;
    int j = idx & 31;
    int h = (idx >> 5) & 15;
    int r = idx >> 9;
    int pos = r & (SEQ - 1);
    float inv = powf(10000.0f, -(float)j / 32.0f);
    float ang = (float)pos * inv;
    float c, s;
    sincosf(ang, &c, &s);
    size_t o = (size_t)r * D_MODEL + h * DH + 2 * j;
    {
        float x1 = Q[o], x2 = Q[o+1];
        Q[o]   =  x1 * c + x2 * s;
        Q[o+1] = -x1 * s + x2 * c;
    }
    {
        float x1 = K[o], x2 = K[o+1];
        K[o]   =  x1 * c + x2 * s;
        K[o+1] = -x1 * s + x2 * c;
    }
}

// ---------------------------------------------------------------------------
// Causal attention, dh=64. One THREAD = one query row (unchanged from R9).
// ---------------------------------------------------------------------------
__global__ void __launch_bounds__(128)
attn_kernel(const float* __restrict__ Q, const float* __restrict__ K,
            const float* __restrict__ V, float* __restrict__ O)
{
    __shared__ float Ks[64][64];
    __shared__ float Vs[64][64];

    const int tid = threadIdx.x;
    const int q0  = blockIdx.x * 128;
    const int q   = q0 + tid;
    const int h   = blockIdx.y, b = blockIdx.z;
    const size_t base = (size_t)b * SEQ * D_MODEL + h * DH;

    float qv[64];
    #pragma unroll
    for (int c = 0; c < 64; c += 4) {
        float4 t = *(const float4*)(Q + base + (size_t)q * D_MODEL + c);
        qv[c] = t.x; qv[c+1] = t.y; qv[c+2] = t.z; qv[c+3] = t.w;
    }

    float acc[64];
    #pragma unroll
    for (int c = 0; c < 64; ++c) acc[c] = 0.f;
    float m = -1e30f, l = 0.f;

    const int ntiles = q0 / 64 + 2;
    for (int t = 0; t < ntiles; ++t) {
        const int n0 = t * 64;
        __syncthreads();
        #pragma unroll
        for (int it = 0; it < 8; ++it) {
            int e = tid + it * 128;
            int row = e >> 4, c4 = (e & 15) * 4;
            *(float4*)&Ks[row][c4] = *(const float4*)(K + base + (size_t)(n0 + row) * D_MODEL + c4);
            *(float4*)&Vs[row][c4] = *(const float4*)(V + base + (size_t)(n0 + row) * D_MODEL + c4);
        }
        __syncthreads();

        const int nmax = min(64, q - n0 + 1);
        for (int n = 0; n < nmax; ++n) {
            float d0 = 0.f, d1 = 0.f, d2 = 0.f, d3 = 0.f;
            #pragma unroll
            for (int c = 0; c < 64; c += 4) {
                float4 kv = *(const float4*)&Ks[n][c];
                d0 = fmaf(qv[c+0], kv.x, d0);
                d1 = fmaf(qv[c+1], kv.y, d1);
                d2 = fmaf(qv[c+2], kv.z, d2);
                d3 = fmaf(qv[c+3], kv.w, d3);
            }
            float s = (d0 + d1 + d2 + d3) * 0.125f;

            float nm    = fmaxf(m, s);
            float alpha = __expf(m - nm);
            float p     = __expf(s - nm);
            l = l * alpha + p;
            m = nm;
            if (alpha != 1.0f) {
                #pragma unroll
                for (int c = 0; c < 64; ++c) acc[c] *= alpha;
            }
            #pragma unroll
            for (int c = 0; c < 64; c += 4) {
                float4 vv = *(const float4*)&Vs[n][c];
                acc[c+0] = fmaf(p, vv.x, acc[c+0]);
                acc[c+1] = fmaf(p, vv.y, acc[c+1]);
                acc[c+2] = fmaf(p, vv.z, acc[c+2]);
                acc[c+3] = fmaf(p, vv.w, acc[c+3]);
            }
        }
    }

    const float inv_l = 1.0f / l;
    #pragma unroll
    for (int c = 0; c < 64; c += 4) {
        float4 v = make_float4(acc[c]*inv_l, acc[c+1]*inv_l, acc[c+2]*inv_l, acc[c+3]*inv_l);
        *(float4*)(O + base + (size_t)q * D_MODEL + c) = v;
    }
}

// ---------------------------------------------------------------------------
extern "C" void kernel_launch(void* const* d_in, const int* in_sizes, int n_in,
                              void* d_out, int out_size)
{
    const float* x  = (const float*)d_in[0];
    const float* Wq = (const float*)d_in[1];
    const float* Wk = (const float*)d_in[2];
    const float* Wv = (const float*)d_in[3];
    const float* Wo = (const float*)d_in[4];
    float* out = (float*)d_out;

    float *qb, *kb, *vb, *ob;
    cudaGetSymbolAddress((void**)&qb, g_Q);
    cudaGetSymbolAddress((void**)&kb, g_K);
    cudaGetSymbolAddress((void**)&vb, g_V);
    cudaGetSymbolAddress((void**)&ob, g_O);

    dim3 ggrd(D_MODEL / 128, ROWS / 128);   // (8, 32)

    gemm_nt_tf32<<<ggrd, 256>>>(x, Wq, qb, ROWS, D_MODEL, D_MODEL);
    gemm_nt_tf32<<<ggrd, 256>>>(x, Wk, kb, ROWS, D_MODEL, D_MODEL);
    gemm_nt_tf32<<<ggrd, 256>>>(x, Wv, vb, ROWS, D_MODEL, D_MODEL);

    int nrope = ROWS * NHEADS * (DH/2);
    rope_neg_kernel<<<(nrope + 255) / 256, 256>>>(qb, kb);

    attn_kernel<<<dim3(SEQ/128, NHEADS, BATCH), 128>>>(qb, kb, vb, ob);

    gemm_nt_tf32<<<ggrd, 256>>>(ob, Wo, out, ROWS, D_MODEL, D_MODEL);
}

// round 11
// speedup vs baseline: 2.1890x; 1.7539x over previous
#include <cuda_runtime.h>
#include <math.h>
#include <stdint.h>

#define D_MODEL 1024
#define SEQ     2048
#define BATCH   2
#define NHEADS  16
#define DH      64
#define ROWS    (BATCH*SEQ)   // 4096

// Scratch (alloc-free: __device__ globals)
__device__ float g_Q[ROWS*D_MODEL];
__device__ float g_K[ROWS*D_MODEL];
__device__ float g_V[ROWS*D_MODEL];
__device__ float g_O[ROWS*D_MODEL];

// ---------------------------------------------------------------------------
// TF32 helpers
// ---------------------------------------------------------------------------
__device__ __forceinline__ uint32_t f2tf32(float x) {
    uint32_t r;
    asm("cvt.rna.tf32.f32 %0, %1;" : "=r"(r) : "f"(x));
    return r;
}
__device__ __forceinline__ float f2tf32f(float x) {
    uint32_t r;
    asm("cvt.rna.tf32.f32 %0, %1;" : "=r"(r) : "f"(x));
    return __uint_as_float(r);
}
__device__ __forceinline__ void mma_tf32(float* d,
                                         uint32_t a0, uint32_t a1, uint32_t a2, uint32_t a3,
                                         uint32_t b0, uint32_t b1) {
    asm volatile(
        "mma.sync.aligned.m16n8k8.row.col.f32.tf32.tf32.f32 "
        "{%0,%1,%2,%3}, {%4,%5,%6,%7}, {%8,%9}, {%0,%1,%2,%3};"
        : "+f"(d[0]), "+f"(d[1]), "+f"(d[2]), "+f"(d[3])
        : "r"(a0), "r"(a1), "r"(a2), "r"(a3), "r"(b0), "r"(b1));
}

// ---------------------------------------------------------------------------
// GEMM (unchanged from R10): 128x128 tile, 256 thr, 2xTF32 compensation,
// double-buffered smem.
// ---------------------------------------------------------------------------
__global__ void __launch_bounds__(256, 1)
gemm_nt_tf32(const float* __restrict__ A, const float* __restrict__ W,
             float* __restrict__ C, int M, int N, int K)
{
    __shared__ float As[2][128][20];
    __shared__ float Ws[2][128][20];

    const int tid  = threadIdx.x;
    const int wid  = tid >> 5;
    const int lane = tid & 31;
    const int gid  = lane >> 2;
    const int tig  = lane & 3;
    const int wm   = (wid & 3) * 32;
    const int wn   = (wid >> 2) * 64;
    const int i0   = blockIdx.y * 128, m0 = blockIdx.x * 128;

    float acc[2][8][4];
    #pragma unroll
    for (int ma = 0; ma < 2; ++ma)
        #pragma unroll
        for (int na = 0; na < 8; ++na)
            #pragma unroll
            for (int c = 0; c < 4; ++c) acc[ma][na][c] = 0.f;

    const int lr = tid >> 1;
    const int lc = (tid & 1) * 8;
    const float* Ap = A + (size_t)(i0 + lr) * K + lc;
    const float* Wp = W + (size_t)(m0 + lr) * K + lc;

    {
        float4 a0v = *(const float4*)(Ap);
        float4 a1v = *(const float4*)(Ap + 4);
        float4 w0v = *(const float4*)(Wp);
        float4 w1v = *(const float4*)(Wp + 4);
        *(float4*)&As[0][lr][lc]     = a0v;
        *(float4*)&As[0][lr][lc + 4] = a1v;
        *(float4*)&Ws[0][lr][lc]     = w0v;
        *(float4*)&Ws[0][lr][lc + 4] = w1v;
    }
    __syncthreads();

    int buf = 0;
    for (int k0 = 0; k0 < K; k0 += 16) {
        const bool has_next = (k0 + 16) < K;
        float4 na0, na1, nw0, nw1;
        if (has_next) {
            na0 = *(const float4*)(Ap + k0 + 16);
            na1 = *(const float4*)(Ap + k0 + 20);
            nw0 = *(const float4*)(Wp + k0 + 16);
            nw1 = *(const float4*)(Wp + k0 + 20);
        }

        #pragma unroll
        for (int ks = 0; ks < 16; ks += 8) {
            uint32_t ah[2][4], al[2][4];
            #pragma unroll
            for (int ma = 0; ma < 2; ++ma) {
                int r = wm + ma * 16 + gid;
                float f0 = As[buf][r][ks + tig];
                float f1 = As[buf][r + 8][ks + tig];
                float f2 = As[buf][r][ks + tig + 4];
                float f3 = As[buf][r + 8][ks + tig + 4];
                ah[ma][0] = f2tf32(f0); al[ma][0] = f2tf32(f0 - __uint_as_float(ah[ma][0]));
                ah[ma][1] = f2tf32(f1); al[ma][1] = f2tf32(f1 - __uint_as_float(ah[ma][1]));
                ah[ma][2] = f2tf32(f2); al[ma][2] = f2tf32(f2 - __uint_as_float(ah[ma][2]));
                ah[ma][3] = f2tf32(f3); al[ma][3] = f2tf32(f3 - __uint_as_float(ah[ma][3]));
            }
            uint32_t bh[8][2], bl[8][2];
            #pragma unroll
            for (int na = 0; na < 8; ++na) {
                int n = wn + na * 8 + gid;
                float f0 = Ws[buf][n][ks + tig];
                float f1 = Ws[buf][n][ks + tig + 4];
                bh[na][0] = f2tf32(f0); bl[na][0] = f2tf32(f0 - __uint_as_float(bh[na][0]));
                bh[na][1] = f2tf32(f1); bl[na][1] = f2tf32(f1 - __uint_as_float(bh[na][1]));
            }
            #pragma unroll
            for (int ma = 0; ma < 2; ++ma)
                #pragma unroll
                for (int na = 0; na < 8; ++na) {
                    mma_tf32(acc[ma][na], ah[ma][0], ah[ma][1], ah[ma][2], ah[ma][3],
                             bh[na][0], bh[na][1]);
                    mma_tf32(acc[ma][na], al[ma][0], al[ma][1], al[ma][2], al[ma][3],
                             bh[na][0], bh[na][1]);
                    mma_tf32(acc[ma][na], ah[ma][0], ah[ma][1], ah[ma][2], ah[ma][3],
                             bl[na][0], bl[na][1]);
                }
        }

        if (has_next) {
            *(float4*)&As[buf ^ 1][lr][lc]     = na0;
            *(float4*)&As[buf ^ 1][lr][lc + 4] = na1;
            *(float4*)&Ws[buf ^ 1][lr][lc]     = nw0;
            *(float4*)&Ws[buf ^ 1][lr][lc + 4] = nw1;
            __syncthreads();
            buf ^= 1;
        }
    }

    #pragma unroll
    for (int ma = 0; ma < 2; ++ma) {
        int r = i0 + wm + ma * 16 + gid;
        #pragma unroll
        for (int na = 0; na < 8; ++na) {
            int cbase = m0 + wn + na * 8 + 2 * tig;
            *(float2*)(C + (size_t)r * N + cbase)       = make_float2(acc[ma][na][0], acc[ma][na][1]);
            *(float2*)(C + (size_t)(r + 8) * N + cbase) = make_float2(acc[ma][na][2], acc[ma][na][3]);
        }
    }
}

// ---------------------------------------------------------------------------
// In-place INTERLEAVED RoPE with NEGATIVE rotation sign, fused Q+K.
// ---------------------------------------------------------------------------
__global__ void rope_neg_kernel(float* __restrict__ Q, float* __restrict__ K)
{
    int idx = blockIdx.x * blockDim.x + threadIdx.x;
    if (idx >= ROWS * NHEADS * (DH/2)) return;
    int j = idx & 31;
    int h = (idx >> 5) & 15;
    int r = idx >> 9;
    int pos = r & (SEQ - 1);
    float inv = powf(10000.0f, -(float)j / 32.0f);
    float ang = (float)pos * inv;
    float c, s;
    sincosf(ang, &c, &s);
    size_t o = (size_t)r * D_MODEL + h * DH + 2 * j;
    {
        float x1 = Q[o], x2 = Q[o+1];
        Q[o]   =  x1 * c + x2 * s;
        Q[o+1] = -x1 * s + x2 * c;
    }
    {
        float x1 = K[o], x2 = K[o+1];
        K[o]   =  x1 * c + x2 * s;
        K[o+1] = -x1 * s + x2 * c;
    }
}

// ---------------------------------------------------------------------------
// Tensor-core causal flash attention, dh=64.
// Block: 256 thr (8 warps), 128 q-rows of one (b,h); warp w owns rows
// [q0+16w, q0+16w+16). K tiles of 64 keys staged in smem as tf32-rounded
// floats (stride 68: b-frag banks 4*gid+tig, conflict-free). V stride 72
// (banks 8*tig+gid, conflict-free). P c-frag -> a-frag via warp shfl.
// Per-warp causal early-out; tile order ascending so row 0 valid first.
// ---------------------------------------------------------------------------
__global__ void __launch_bounds__(256, 1)
attn_mma(const float* __restrict__ Q, const float* __restrict__ K,
         const float* __restrict__ V, float* __restrict__ O)
{
    __shared__ float Ks[64][68];
    __shared__ float Vs[64][72];

    const int tid  = threadIdx.x;
    const int w    = tid >> 5;
    const int lane = tid & 31;
    const int gid  = lane >> 2;
    const int tig  = lane & 3;
    const int q0   = blockIdx.x * 128;
    const int h    = blockIdx.y, b = blockIdx.z;
    const int qbase = q0 + w * 16;
    const size_t base = (size_t)b * SEQ * D_MODEL + h * DH;

    // Q fragments (tf32), loaded once: qf[kstep][0..3]
    uint32_t qf[8][4];
    {
        const float* qr0 = Q + base + (size_t)(qbase + gid) * D_MODEL;
        const float* qr1 = Q + base + (size_t)(qbase + gid + 8) * D_MODEL;
        #pragma unroll
        for (int ks = 0; ks < 8; ++ks) {
            int col = ks * 8 + tig;
            qf[ks][0] = f2tf32(qr0[col]);
            qf[ks][1] = f2tf32(qr1[col]);
            qf[ks][2] = f2tf32(qr0[col + 4]);
            qf[ks][3] = f2tf32(qr1[col + 4]);
        }
    }

    float oacc[8][4];
    #pragma unroll
    for (int na = 0; na < 8; ++na)
        #pragma unroll
        for (int c = 0; c < 4; ++c) oacc[na][c] = 0.f;
    float m1 = -1e30f, m2 = -1e30f, l1 = 0.f, l2 = 0.f;

    const int ntiles = q0 / 64 + 2;
    for (int t = 0; t < ntiles; ++t) {
        const int n0 = t * 64;
        __syncthreads();
        // Stage K,V tiles (64x64), tf32-rounded at staging time.
        #pragma unroll
        for (int it = 0; it < 4; ++it) {
            int e = tid + it * 256;          // 0..1023
            int row = e >> 4, c4 = (e & 15) * 4;
            float4 kv = *(const float4*)(K + base + (size_t)(n0 + row) * D_MODEL + c4);
            float4 vv = *(const float4*)(V + base + (size_t)(n0 + row) * D_MODEL + c4);
            kv.x = f2tf32f(kv.x); kv.y = f2tf32f(kv.y);
            kv.z = f2tf32f(kv.z); kv.w = f2tf32f(kv.w);
            vv.x = f2tf32f(vv.x); vv.y = f2tf32f(vv.y);
            vv.z = f2tf32f(vv.z); vv.w = f2tf32f(vv.w);
            *(float4*)&Ks[row][c4] = kv;
            *(float4*)&Vs[row][c4] = vv;
        }
        __syncthreads();

        if (n0 > qbase + 15) continue;   // tile fully above this warp's rows

        // S = Q K^T  (16 x 64 per warp)
        float sacc[8][4];
        #pragma unroll
        for (int na = 0; na < 8; ++na)
            #pragma unroll
            for (int c = 0; c < 4; ++c) sacc[na][c] = 0.f;
        #pragma unroll
        for (int ks = 0; ks < 8; ++ks) {
            #pragma unroll
            for (int na = 0; na < 8; ++na) {
                uint32_t b0 = __float_as_uint(Ks[na * 8 + gid][ks * 8 + tig]);
                uint32_t b1 = __float_as_uint(Ks[na * 8 + gid][ks * 8 + tig + 4]);
                mma_tf32(sacc[na], qf[ks][0], qf[ks][1], qf[ks][2], qf[ks][3], b0, b1);
            }
        }

        // scale + causal mask + online softmax (2 rows per thread)
        const bool need_mask = (n0 + 63 > qbase);
        const int row1 = qbase + gid, row2 = row1 + 8;
        float mx1 = -1e30f, mx2 = -1e30f;
        #pragma unroll
        for (int na = 0; na < 8; ++na) {
            int col0 = n0 + na * 8 + 2 * tig;
            float s0 = sacc[na][0] * 0.125f;
            float s1 = sacc[na][1] * 0.125f;
            float s2 = sacc[na][2] * 0.125f;
            float s3 = sacc[na][3] * 0.125f;
            if (need_mask) {
                if (col0     > row1) s0 = -1e30f;
                if (col0 + 1 > row1) s1 = -1e30f;
                if (col0     > row2) s2 = -1e30f;
                if (col0 + 1 > row2) s3 = -1e30f;
            }
            sacc[na][0] = s0; sacc[na][1] = s1; sacc[na][2] = s2; sacc[na][3] = s3;
            mx1 = fmaxf(mx1, fmaxf(s0, s1));
            mx2 = fmaxf(mx2, fmaxf(s2, s3));
        }
        mx1 = fmaxf(mx1, __shfl_xor_sync(0xffffffffu, mx1, 1));
        mx1 = fmaxf(mx1, __shfl_xor_sync(0xffffffffu, mx1, 2));
        mx2 = fmaxf(mx2, __shfl_xor_sync(0xffffffffu, mx2, 1));
        mx2 = fmaxf(mx2, __shfl_xor_sync(0xffffffffu, mx2, 2));

        float m1n = fmaxf(m1, mx1), m2n = fmaxf(m2, mx2);
        float a1 = __expf(m1 - m1n), a2 = __expf(m2 - m2n);
        float rs1 = 0.f, rs2 = 0.f;
        #pragma unroll
        for (int na = 0; na < 8; ++na) {
            float p0 = __expf(sacc[na][0] - m1n);
            float p1 = __expf(sacc[na][1] - m1n);
            float p2 = __expf(sacc[na][2] - m2n);
            float p3 = __expf(sacc[na][3] - m2n);
            sacc[na][0] = p0; sacc[na][1] = p1; sacc[na][2] = p2; sacc[na][3] = p3;
            rs1 += p0 + p1; rs2 += p2 + p3;
        }
        rs1 += __shfl_xor_sync(0xffffffffu, rs1, 1);
        rs1 += __shfl_xor_sync(0xffffffffu, rs1, 2);
        rs2 += __shfl_xor_sync(0xffffffffu, rs2, 1);
        rs2 += __shfl_xor_sync(0xffffffffu, rs2, 2);
        l1 = l1 * a1 + rs1;  m1 = m1n;
        l2 = l2 * a2 + rs2;  m2 = m2n;
        #pragma unroll
        for (int na = 0; na < 8; ++na) {
            oacc[na][0] *= a1; oacc[na][1] *= a1;
            oacc[na][2] *= a2; oacc[na][3] *= a2;
        }

        // O += P V : P c-frag -> a-frag via shfl, then MMA over 8 dim-atoms
        const int src_lo = (gid << 2) + (tig >> 1);
        const int src_hi = src_lo + 2;
        const bool odd = tig & 1;
        #pragma unroll
        for (int kp = 0; kp < 8; ++kp) {
            float v00 = __shfl_sync(0xffffffffu, sacc[kp][0], src_lo);
            float v01 = __shfl_sync(0xffffffffu, sacc[kp][1], src_lo);
            float v10 = __shfl_sync(0xffffffffu, sacc[kp][2], src_lo);
            float v11 = __shfl_sync(0xffffffffu, sacc[kp][3], src_lo);
            float v20 = __shfl_sync(0xffffffffu, sacc[kp][0], src_hi);
            float v21 = __shfl_sync(0xffffffffu, sacc[kp][1], src_hi);
            float v30 = __shfl_sync(0xffffffffu, sacc[kp][2], src_hi);
            float v31 = __shfl_sync(0xffffffffu, sacc[kp][3], src_hi);
            uint32_t pa0 = f2tf32(odd ? v01 : v00);
            uint32_t pa1 = f2tf32(odd ? v11 : v10);
            uint32_t pa2 = f2tf32(odd ? v21 : v20);
            uint32_t pa3 = f2tf32(odd ? v31 : v30);
            #pragma unroll
            for (int na = 0; na < 8; ++na) {
                uint32_t b0 = __float_as_uint(Vs[kp * 8 + tig][na * 8 + gid]);
                uint32_t b1 = __float_as_uint(Vs[kp * 8 + tig + 4][na * 8 + gid]);
                mma_tf32(oacc[na], pa0, pa1, pa2, pa3, b0, b1);
            }
        }
    }

    // Epilogue: normalize and store
    const float inv1 = 1.0f / l1, inv2 = 1.0f / l2;
    float* o1 = O + base + (size_t)(qbase + gid) * D_MODEL;
    float* o2 = O + base + (size_t)(qbase + gid + 8) * D_MODEL;
    #pragma unroll
    for (int na = 0; na < 8; ++na) {
        int col = na * 8 + 2 * tig;
        *(float2*)(o1 + col) = make_float2(oacc[na][0] * inv1, oacc[na][1] * inv1);
        *(float2*)(o2 + col) = make_float2(oacc[na][2] * inv2, oacc[na][3] * inv2);
    }
}

// ---------------------------------------------------------------------------
extern "C" void kernel_launch(void* const* d_in, const int* in_sizes, int n_in,
                              void* d_out, int out_size)
{
    const float* x  = (const float*)d_in[0];
    const float* Wq = (const float*)d_in[1];
    const float* Wk = (const float*)d_in[2];
    const float* Wv = (const float*)d_in[3];
    const float* Wo = (const float*)d_in[4];
    float* out = (float*)d_out;

    float *qb, *kb, *vb, *ob;
    cudaGetSymbolAddress((void**)&qb, g_Q);
    cudaGetSymbolAddress((void**)&kb, g_K);
    cudaGetSymbolAddress((void**)&vb, g_V);
    cudaGetSymbolAddress((void**)&ob, g_O);

    dim3 ggrd(D_MODEL / 128, ROWS / 128);   // (8, 32)

    gemm_nt_tf32<<<ggrd, 256>>>(x, Wq, qb, ROWS, D_MODEL, D_MODEL);
    gemm_nt_tf32<<<ggrd, 256>>>(x, Wk, kb, ROWS, D_MODEL, D_MODEL);
    gemm_nt_tf32<<<ggrd, 256>>>(x, Wv, vb, ROWS, D_MODEL, D_MODEL);

    int nrope = ROWS * NHEADS * (DH/2);
    rope_neg_kernel<<<(nrope + 255) / 256, 256>>>(qb, kb);

    attn_mma<<<dim3(SEQ/128, NHEADS, BATCH), 256>>>(qb, kb, vb, ob);

    gemm_nt_tf32<<<ggrd, 256>>>(ob, Wo, out, ROWS, D_MODEL, D_MODEL);
}

// round 12
// speedup vs baseline: 2.8307x; 1.2931x over previous
#include <cuda_runtime.h>
#include <math.h>
#include <stdint.h>

#define D_MODEL 1024
#define SEQ     2048
#define BATCH   2
#define NHEADS  16
#define DH      64
#define ROWS    (BATCH*SEQ)   // 4096

// Scratch (alloc-free: __device__ globals)
__device__ float g_Q[ROWS*D_MODEL];
__device__ float g_K[ROWS*D_MODEL];
__device__ float g_V[ROWS*D_MODEL];
__device__ float g_O[ROWS*D_MODEL];

// ---------------------------------------------------------------------------
// Numeric helpers
// ---------------------------------------------------------------------------
__device__ __forceinline__ uint32_t f2tf32(float x) {
    uint32_t r;
    asm("cvt.rna.tf32.f32 %0, %1;" : "=r"(r) : "f"(x));
    return r;
}
__device__ __forceinline__ float f2tf32f(float x) {
    uint32_t r;
    asm("cvt.rna.tf32.f32 %0, %1;" : "=r"(r) : "f"(x));
    return __uint_as_float(r);
}
__device__ __forceinline__ void mma_tf32(float* d,
                                         uint32_t a0, uint32_t a1, uint32_t a2, uint32_t a3,
                                         uint32_t b0, uint32_t b1) {
    asm volatile(
        "mma.sync.aligned.m16n8k8.row.col.f32.tf32.tf32.f32 "
        "{%0,%1,%2,%3}, {%4,%5,%6,%7}, {%8,%9}, {%0,%1,%2,%3};"
        : "+f"(d[0]), "+f"(d[1]), "+f"(d[2]), "+f"(d[3])
        : "r"(a0), "r"(a1), "r"(a2), "r"(a3), "r"(b0), "r"(b1));
}
__device__ __forceinline__ void mma_bf16(float* d,
                                         uint32_t a0, uint32_t a1, uint32_t a2, uint32_t a3,
                                         uint32_t b0, uint32_t b1) {
    asm volatile(
        "mma.sync.aligned.m16n8k16.row.col.f32.bf16.bf16.f32 "
        "{%0,%1,%2,%3}, {%4,%5,%6,%7}, {%8,%9}, {%0,%1,%2,%3};"
        : "+f"(d[0]), "+f"(d[1]), "+f"(d[2]), "+f"(d[3])
        : "r"(a0), "r"(a1), "r"(a2), "r"(a3), "r"(b0), "r"(b1));
}
// Split two floats into packed bf16x2 hi (rounded) and lo (exact residual,
// then bf16-rounded). Low 16 bits hold f0 (the even-k element).
__device__ __forceinline__ void split2(float f0, float f1, uint32_t& hi, uint32_t& lo) {
    asm("cvt.rn.bf16x2.f32 %0, %1, %2;" : "=r"(hi) : "f"(f1), "f"(f0));
    float r0 = f0 - __uint_as_float(hi << 16);
    float r1 = f1 - __uint_as_float(hi & 0xFFFF0000u);
    asm("cvt.rn.bf16x2.f32 %0, %1, %2;" : "=r"(lo) : "f"(r1), "f"(r0));
}

// ---------------------------------------------------------------------------
// C[i][m] = sum_k A[i][k] * W[m][k] via bf16 3-term split on m16n8k16.
// Tile 128x128, 256 threads (8 warps: 4m x 2n, warp tile 32x64), BK=16.
// Floats split hi/lo ONCE at staging into packed bf16x2 k-pair words.
// acc += a_hi*b_hi + a_hi*b_lo + a_lo*b_hi  (dropped a_lo*b_lo ~ 2^-18).
// Smem rows of 12 u32: 12*gid+tig spans all 32 banks -> conflict-free.
// ---------------------------------------------------------------------------
__global__ void __launch_bounds__(256, 1)
gemm_nt_bf16(const float* __restrict__ A, const float* __restrict__ W,
             float* __restrict__ C, int M, int N, int K)
{
    __shared__ uint32_t Ah[128][12];
    __shared__ uint32_t Al[128][12];
    __shared__ uint32_t Bh[128][12];
    __shared__ uint32_t Bl[128][12];

    const int tid  = threadIdx.x;
    const int wid  = tid >> 5;
    const int lane = tid & 31;
    const int gid  = lane >> 2;       // 0..7
    const int tig  = lane & 3;        // 0..3
    const int wm   = (wid & 3) * 32;
    const int wn   = (wid >> 2) * 64;
    const int i0   = blockIdx.y * 128, m0 = blockIdx.x * 128;

    float acc[2][8][4];
    #pragma unroll
    for (int ma = 0; ma < 2; ++ma)
        #pragma unroll
        for (int na = 0; na < 8; ++na)
            #pragma unroll
            for (int c = 0; c < 4; ++c) acc[ma][na][c] = 0.f;

    // staging: 256 threads cover 128 rows x 16 floats (8 floats = 4 k-pairs each)
    const int lr = tid >> 1;               // 0..127
    const int lp = (tid & 1) * 4;          // pair offset 0 or 4
    const float* Ap = A + (size_t)(i0 + lr) * K + lp * 2;
    const float* Wp = W + (size_t)(m0 + lr) * K + lp * 2;

    for (int k0 = 0; k0 < K; k0 += 16) {
        float4 av0 = *(const float4*)(Ap + k0);
        float4 av1 = *(const float4*)(Ap + k0 + 4);
        float4 wv0 = *(const float4*)(Wp + k0);
        float4 wv1 = *(const float4*)(Wp + k0 + 4);
        __syncthreads();    // previous chunk fully consumed
        split2(av0.x, av0.y, Ah[lr][lp+0], Al[lr][lp+0]);
        split2(av0.z, av0.w, Ah[lr][lp+1], Al[lr][lp+1]);
        split2(av1.x, av1.y, Ah[lr][lp+2], Al[lr][lp+2]);
        split2(av1.z, av1.w, Ah[lr][lp+3], Al[lr][lp+3]);
        split2(wv0.x, wv0.y, Bh[lr][lp+0], Bl[lr][lp+0]);
        split2(wv0.z, wv0.w, Bh[lr][lp+1], Bl[lr][lp+1]);
        split2(wv1.x, wv1.y, Bh[lr][lp+2], Bl[lr][lp+2]);
        split2(wv1.z, wv1.w, Bh[lr][lp+3], Bl[lr][lp+3]);
        __syncthreads();

        // B fragments for all 8 n-atoms
        uint32_t bh[8][2], bl[8][2];
        #pragma unroll
        for (int na = 0; na < 8; ++na) {
            int n = wn + na * 8 + gid;
            bh[na][0] = Bh[n][tig];     bh[na][1] = Bh[n][tig + 4];
            bl[na][0] = Bl[n][tig];     bl[na][1] = Bl[n][tig + 4];
        }
        #pragma unroll
        for (int ma = 0; ma < 2; ++ma) {
            int r = wm + ma * 16 + gid;
            uint32_t ah0 = Ah[r][tig],     ah1 = Ah[r + 8][tig];
            uint32_t ah2 = Ah[r][tig + 4], ah3 = Ah[r + 8][tig + 4];
            uint32_t al0 = Al[r][tig],     al1 = Al[r + 8][tig];
            uint32_t al2 = Al[r][tig + 4], al3 = Al[r + 8][tig + 4];
            #pragma unroll
            for (int na = 0; na < 8; ++na) {
                mma_bf16(acc[ma][na], ah0, ah1, ah2, ah3, bh[na][0], bh[na][1]);
                mma_bf16(acc[ma][na], ah0, ah1, ah2, ah3, bl[na][0], bl[na][1]);
                mma_bf16(acc[ma][na], al0, al1, al2, al3, bh[na][0], bh[na][1]);
            }
        }
    }

    #pragma unroll
    for (int ma = 0; ma < 2; ++ma) {
        int r = i0 + wm + ma * 16 + gid;
        #pragma unroll
        for (int na = 0; na < 8; ++na) {
            int cbase = m0 + wn + na * 8 + 2 * tig;
            *(float2*)(C + (size_t)r * N + cbase)       = make_float2(acc[ma][na][0], acc[ma][na][1]);
            *(float2*)(C + (size_t)(r + 8) * N + cbase) = make_float2(acc[ma][na][2], acc[ma][na][3]);
        }
    }
}

// ---------------------------------------------------------------------------
// In-place INTERLEAVED RoPE with NEGATIVE rotation sign, fused Q+K.
// ---------------------------------------------------------------------------
__global__ void rope_neg_kernel(float* __restrict__ Q, float* __restrict__ K)
{
    int idx = blockIdx.x * blockDim.x + threadIdx.x;
    if (idx >= ROWS * NHEADS * (DH/2)) return;
    int j = idx & 31;
    int h = (idx >> 5) & 15;
    int r = idx >> 9;
    int pos = r & (SEQ - 1);
    float inv = powf(10000.0f, -(float)j / 32.0f);
    float ang = (float)pos * inv;
    float c, s;
    sincosf(ang, &c, &s);
    size_t o = (size_t)r * D_MODEL + h * DH + 2 * j;
    {
        float x1 = Q[o], x2 = Q[o+1];
        Q[o]   =  x1 * c + x2 * s;
        Q[o+1] = -x1 * s + x2 * c;
    }
    {
        float x1 = K[o], x2 = K[o+1];
        K[o]   =  x1 * c + x2 * s;
        K[o+1] = -x1 * s + x2 * c;
    }
}

// ---------------------------------------------------------------------------
// Tensor-core causal flash attention, dh=64 (unchanged from R11).
// ---------------------------------------------------------------------------
__global__ void __launch_bounds__(256, 1)
attn_mma(const float* __restrict__ Q, const float* __restrict__ K,
         const float* __restrict__ V, float* __restrict__ O)
{
    __shared__ float Ks[64][68];
    __shared__ float Vs[64][72];

    const int tid  = threadIdx.x;
    const int w    = tid >> 5;
    const int lane = tid & 31;
    const int gid  = lane >> 2;
    const int tig  = lane & 3;
    const int q0   = blockIdx.x * 128;
    const int h    = blockIdx.y, b = blockIdx.z;
    const int qbase = q0 + w * 16;
    const size_t base = (size_t)b * SEQ * D_MODEL + h * DH;

    uint32_t qf[8][4];
    {
        const float* qr0 = Q + base + (size_t)(qbase + gid) * D_MODEL;
        const float* qr1 = Q + base + (size_t)(qbase + gid + 8) * D_MODEL;
        #pragma unroll
        for (int ks = 0; ks < 8; ++ks) {
            int col = ks * 8 + tig;
            qf[ks][0] = f2tf32(qr0[col]);
            qf[ks][1] = f2tf32(qr1[col]);
            qf[ks][2] = f2tf32(qr0[col + 4]);
            qf[ks][3] = f2tf32(qr1[col + 4]);
        }
    }

    float oacc[8][4];
    #pragma unroll
    for (int na = 0; na < 8; ++na)
        #pragma unroll
        for (int c = 0; c < 4; ++c) oacc[na][c] = 0.f;
    float m1 = -1e30f, m2 = -1e30f, l1 = 0.f, l2 = 0.f;

    const int ntiles = q0 / 64 + 2;
    for (int t = 0; t < ntiles; ++t) {
        const int n0 = t * 64;
        __syncthreads();
        #pragma unroll
        for (int it = 0; it < 4; ++it) {
            int e = tid + it * 256;
            int row = e >> 4, c4 = (e & 15) * 4;
            float4 kv = *(const float4*)(K + base + (size_t)(n0 + row) * D_MODEL + c4);
            float4 vv = *(const float4*)(V + base + (size_t)(n0 + row) * D_MODEL + c4);
            kv.x = f2tf32f(kv.x); kv.y = f2tf32f(kv.y);
            kv.z = f2tf32f(kv.z); kv.w = f2tf32f(kv.w);
            vv.x = f2tf32f(vv.x); vv.y = f2tf32f(vv.y);
            vv.z = f2tf32f(vv.z); vv.w = f2tf32f(vv.w);
            *(float4*)&Ks[row][c4] = kv;
            *(float4*)&Vs[row][c4] = vv;
        }
        __syncthreads();

        if (n0 > qbase + 15) continue;

        float sacc[8][4];
        #pragma unroll
        for (int na = 0; na < 8; ++na)
            #pragma unroll
            for (int c = 0; c < 4; ++c) sacc[na][c] = 0.f;
        #pragma unroll
        for (int ks = 0; ks < 8; ++ks) {
            #pragma unroll
            for (int na = 0; na < 8; ++na) {
                uint32_t b0 = __float_as_uint(Ks[na * 8 + gid][ks * 8 + tig]);
                uint32_t b1 = __float_as_uint(Ks[na * 8 + gid][ks * 8 + tig + 4]);
                mma_tf32(sacc[na], qf[ks][0], qf[ks][1], qf[ks][2], qf[ks][3], b0, b1);
            }
        }

        const bool need_mask = (n0 + 63 > qbase);
        const int row1 = qbase + gid, row2 = row1 + 8;
        float mx1 = -1e30f, mx2 = -1e30f;
        #pragma unroll
        for (int na = 0; na < 8; ++na) {
            int col0 = n0 + na * 8 + 2 * tig;
            float s0 = sacc[na][0] * 0.125f;
            float s1 = sacc[na][1] * 0.125f;
            float s2 = sacc[na][2] * 0.125f;
            float s3 = sacc[na][3] * 0.125f;
            if (need_mask) {
                if (col0     > row1) s0 = -1e30f;
                if (col0 + 1 > row1) s1 = -1e30f;
                if (col0     > row2) s2 = -1e30f;
                if (col0 + 1 > row2) s3 = -1e30f;
            }
            sacc[na][0] = s0; sacc[na][1] = s1; sacc[na][2] = s2; sacc[na][3] = s3;
            mx1 = fmaxf(mx1, fmaxf(s0, s1));
            mx2 = fmaxf(mx2, fmaxf(s2, s3));
        }
        mx1 = fmaxf(mx1, __shfl_xor_sync(0xffffffffu, mx1, 1));
        mx1 = fmaxf(mx1, __shfl_xor_sync(0xffffffffu, mx1, 2));
        mx2 = fmaxf(mx2, __shfl_xor_sync(0xffffffffu, mx2, 1));
        mx2 = fmaxf(mx2, __shfl_xor_sync(0xffffffffu, mx2, 2));

        float m1n = fmaxf(m1, mx1), m2n = fmaxf(m2, mx2);
        float a1 = __expf(m1 - m1n), a2 = __expf(m2 - m2n);
        float rs1 = 0.f, rs2 = 0.f;
        #pragma unroll
        for (int na = 0; na < 8; ++na) {
            float p0 = __expf(sacc[na][0] - m1n);
            float p1 = __expf(sacc[na][1] - m1n);
            float p2 = __expf(sacc[na][2] - m2n);
            float p3 = __expf(sacc[na][3] - m2n);
            sacc[na][0] = p0; sacc[na][1] = p1; sacc[na][2] = p2; sacc[na][3] = p3;
            rs1 += p0 + p1; rs2 += p2 + p3;
        }
        rs1 += __shfl_xor_sync(0xffffffffu, rs1, 1);
        rs1 += __shfl_xor_sync(0xffffffffu, rs1, 2);
        rs2 += __shfl_xor_sync(0xffffffffu, rs2, 1);
        rs2 += __shfl_xor_sync(0xffffffffu, rs2, 2);
        l1 = l1 * a1 + rs1;  m1 = m1n;
        l2 = l2 * a2 + rs2;  m2 = m2n;
        #pragma unroll
        for (int na = 0; na < 8; ++na) {
            oacc[na][0] *= a1; oacc[na][1] *= a1;
            oacc[na][2] *= a2; oacc[na][3] *= a2;
        }

        const int src_lo = (gid << 2) + (tig >> 1);
        const int src_hi = src_lo + 2;
        const bool odd = tig & 1;
        #pragma unroll
        for (int kp = 0; kp < 8; ++kp) {
            float v00 = __shfl_sync(0xffffffffu, sacc[kp][0], src_lo);
            float v01 = __shfl_sync(0xffffffffu, sacc[kp][1], src_lo);
            float v10 = __shfl_sync(0xffffffffu, sacc[kp][2], src_lo);
            float v11 = __shfl_sync(0xffffffffu, sacc[kp][3], src_lo);
            float v20 = __shfl_sync(0xffffffffu, sacc[kp][0], src_hi);
            float v21 = __shfl_sync(0xffffffffu, sacc[kp][1], src_hi);
            float v30 = __shfl_sync(0xffffffffu, sacc[kp][2], src_hi);
            float v31 = __shfl_sync(0xffffffffu, sacc[kp][3], src_hi);
            uint32_t pa0 = f2tf32(odd ? v01 : v00);
            uint32_t pa1 = f2tf32(odd ? v11 : v10);
            uint32_t pa2 = f2tf32(odd ? v21 : v20);
            uint32_t pa3 = f2tf32(odd ? v31 : v30);
            #pragma unroll
            for (int na = 0; na < 8; ++na) {
                uint32_t b0 = __float_as_uint(Vs[kp * 8 + tig][na * 8 + gid]);
                uint32_t b1 = __float_as_uint(Vs[kp * 8 + tig + 4][na * 8 + gid]);
                mma_tf32(oacc[na], pa0, pa1, pa2, pa3, b0, b1);
            }
        }
    }

    const float inv1 = 1.0f / l1, inv2 = 1.0f / l2;
    float* o1 = O + base + (size_t)(qbase + gid) * D_MODEL;
    float* o2 = O + base + (size_t)(qbase + gid + 8) * D_MODEL;
    #pragma unroll
    for (int na = 0; na < 8; ++na) {
        int col = na * 8 + 2 * tig;
        *(float2*)(o1 + col) = make_float2(oacc[na][0] * inv1, oacc[na][1] * inv1);
        *(float2*)(o2 + col) = make_float2(oacc[na][2] * inv2, oacc[na][3] * inv2);
    }
}

// ---------------------------------------------------------------------------
extern "C" void kernel_launch(void* const* d_in, const int* in_sizes, int n_in,
                              void* d_out, int out_size)
{
    const float* x  = (const float*)d_in[0];
    const float* Wq = (const float*)d_in[1];
    const float* Wk = (const float*)d_in[2];
    const float* Wv = (const float*)d_in[3];
    const float* Wo = (const float*)d_in[4];
    float* out = (float*)d_out;

    float *qb, *kb, *vb, *ob;
    cudaGetSymbolAddress((void**)&qb, g_Q);
    cudaGetSymbolAddress((void**)&kb, g_K);
    cudaGetSymbolAddress((void**)&vb, g_V);
    cudaGetSymbolAddress((void**)&ob, g_O);

    dim3 ggrd(D_MODEL / 128, ROWS / 128);   // (8, 32)

    gemm_nt_bf16<<<ggrd, 256>>>(x, Wq, qb, ROWS, D_MODEL, D_MODEL);
    gemm_nt_bf16<<<ggrd, 256>>>(x, Wk, kb, ROWS, D_MODEL, D_MODEL);
    gemm_nt_bf16<<<ggrd, 256>>>(x, Wv, vb, ROWS, D_MODEL, D_MODEL);

    int nrope = ROWS * NHEADS * (DH/2);
    rope_neg_kernel<<<(nrope + 255) / 256, 256>>>(qb, kb);

    attn_mma<<<dim3(SEQ/128, NHEADS, BATCH), 256>>>(qb, kb, vb, ob);

    gemm_nt_bf16<<<ggrd, 256>>>(ob, Wo, out, ROWS, D_MODEL, D_MODEL);
}

// round 14
// speedup vs baseline: 3.0057x; 1.0618x over previous
#include <cuda_runtime.h>
#include <math.h>
#include <stdint.h>

#define D_MODEL 1024
#define SEQ     2048
#define BATCH   2
#define NHEADS  16
#define DH      64
#define ROWS    (BATCH*SEQ)   // 4096

// ---------------------------------------------------------------------------
// Scratch (alloc-free: __device__ globals)
// ---------------------------------------------------------------------------
__device__ float g_Q[ROWS*D_MODEL];
__device__ float g_K[ROWS*D_MODEL];
__device__ float g_V[ROWS*D_MODEL];
__device__ float g_O[ROWS*D_MODEL];
// bf16 hi/lo splits, packed as uint32 = bf16x2 (low 16 bits = even-k element)
__device__ uint32_t g_xh[ROWS*D_MODEL/2],     g_xl[ROWS*D_MODEL/2];
__device__ uint32_t g_wqh[D_MODEL*D_MODEL/2], g_wql[D_MODEL*D_MODEL/2];
__device__ uint32_t g_wkh[D_MODEL*D_MODEL/2], g_wkl[D_MODEL*D_MODEL/2];
__device__ uint32_t g_wvh[D_MODEL*D_MODEL/2], g_wvl[D_MODEL*D_MODEL/2];
__device__ uint32_t g_woh[D_MODEL*D_MODEL/2], g_wol[D_MODEL*D_MODEL/2];
__device__ uint32_t g_oh[ROWS*D_MODEL/2],     g_ol[ROWS*D_MODEL/2];

// ---------------------------------------------------------------------------
// Numeric / PTX helpers (legacy mma.sync only — tcgen05 unavailable at the
// harness's compute_103 PTX target)
// ---------------------------------------------------------------------------
__device__ __forceinline__ uint32_t f2tf32(float x) {
    uint32_t r; asm("cvt.rna.tf32.f32 %0, %1;" : "=r"(r) : "f"(x)); return r;
}
__device__ __forceinline__ float f2tf32f(float x) {
    uint32_t r; asm("cvt.rna.tf32.f32 %0, %1;" : "=r"(r) : "f"(x));
    return __uint_as_float(r);
}
__device__ __forceinline__ void mma_tf32(float* d,
                                         uint32_t a0, uint32_t a1, uint32_t a2, uint32_t a3,
                                         uint32_t b0, uint32_t b1) {
    asm volatile(
        "mma.sync.aligned.m16n8k8.row.col.f32.tf32.tf32.f32 "
        "{%0,%1,%2,%3}, {%4,%5,%6,%7}, {%8,%9}, {%0,%1,%2,%3};"
        : "+f"(d[0]), "+f"(d[1]), "+f"(d[2]), "+f"(d[3])
        : "r"(a0), "r"(a1), "r"(a2), "r"(a3), "r"(b0), "r"(b1));
}
__device__ __forceinline__ void mma_bf16(float* d,
                                         uint32_t a0, uint32_t a1, uint32_t a2, uint32_t a3,
                                         uint32_t b0, uint32_t b1) {
    asm volatile(
        "mma.sync.aligned.m16n8k16.row.col.f32.bf16.bf16.f32 "
        "{%0,%1,%2,%3}, {%4,%5,%6,%7}, {%8,%9}, {%0,%1,%2,%3};"
        : "+f"(d[0]), "+f"(d[1]), "+f"(d[2]), "+f"(d[3])
        : "r"(a0), "r"(a1), "r"(a2), "r"(a3), "r"(b0), "r"(b1));
}
__device__ __forceinline__ void split2(float f0, float f1, uint32_t& hi, uint32_t& lo) {
    asm("cvt.rn.bf16x2.f32 %0, %1, %2;" : "=r"(hi) : "f"(f1), "f"(f0));
    float r0 = f0 - __uint_as_float(hi << 16);
    float r1 = f1 - __uint_as_float(hi & 0xFFFF0000u);
    asm("cvt.rn.bf16x2.f32 %0, %1, %2;" : "=r"(lo) : "f"(r1), "f"(r0));
}
__device__ __forceinline__ uint32_t smem_u32(const void* p) {
    uint32_t a;
    asm("{ .reg .u64 t; cvta.to.shared.u64 t, %1; cvt.u32.u64 %0, t; }" : "=r"(a) : "l"(p));
    return a;
}
__device__ __forceinline__ void cp16(uint32_t s, const void* g) {
    asm volatile("cp.async.cg.shared.global [%0], [%1], 16;" :: "r"(s), "l"(g) : "memory");
}
#define CP_COMMIT() asm volatile("cp.async.commit_group;" ::: "memory")
#define CP_WAIT1()  asm volatile("cp.async.wait_group 1;" ::: "memory")
#define CP_WAIT0()  asm volatile("cp.async.wait_group 0;" ::: "memory")

// ---------------------------------------------------------------------------
// Split kernel: float -> bf16 hi/lo packed pairs (hoisted out of the GEMM).
// ---------------------------------------------------------------------------
__global__ void split_bf16(const float4* __restrict__ in, uint2* __restrict__ hi,
                           uint2* __restrict__ lo, int n4)
{
    int i = blockIdx.x * blockDim.x + threadIdx.x;
    if (i >= n4) return;
    float4 v = in[i];
    uint32_t h0, l0, h1, l1;
    split2(v.x, v.y, h0, l0);
    split2(v.z, v.w, h1, l1);
    hi[i] = make_uint2(h0, h1);
    lo[i] = make_uint2(l0, l1);
}

// ---------------------------------------------------------------------------
// GEMM: C[i][m] = sum_k A[i][k]*W[m][k] on pre-split bf16 hi/lo.
// Tile 128x128, 256 thr (8 warps: 4m x 2n, warp tile 32x64), k16 chunks,
// cp.async double-buffered. acc += ah*bh + ah*bl + al*bh  (~2^-18 scheme,
// identical numerics to R12). Smem tiles uint32[128][12]: 12*gid+tig spans
// all 32 banks (proven in R12). Occupancy 2 (48KB dyn smem, <=128 regs).
// z selects (B, C) for the fused QKV launch.
// ---------------------------------------------------------------------------
#define TILE_W    12
#define TILE_U32  (128*TILE_W)        // 1536 u32 = 6KB
#define BUF_U32   (4*TILE_U32)        // Ah,Al,Bh,Bl = 24KB
#define GEMM_SMEM (2*BUF_U32*4)       // 49152 B
#define NCHUNK    64                  // K/16

__global__ void __launch_bounds__(256, 2)
gemm_nt_pre(const uint4* __restrict__ Ah, const uint4* __restrict__ Al,
            const uint4* __restrict__ Bh0, const uint4* __restrict__ Bl0,
            const uint4* __restrict__ Bh1, const uint4* __restrict__ Bl1,
            const uint4* __restrict__ Bh2, const uint4* __restrict__ Bl2,
            float* __restrict__ C0, float* __restrict__ C1, float* __restrict__ C2)
{
    extern __shared__ uint32_t sm[];
    const int tid  = threadIdx.x;
    const int wid  = tid >> 5;
    const int lane = tid & 31;
    const int gid  = lane >> 2;       // 0..7
    const int tig  = lane & 3;        // 0..3
    const int wm   = (wid & 3) * 32;
    const int wn   = (wid >> 2) * 64;
    const int z    = blockIdx.z;
    const uint4* Bh = (z == 0) ? Bh0 : (z == 1) ? Bh1 : Bh2;
    const uint4* Bl = (z == 0) ? Bl0 : (z == 1) ? Bl1 : Bl2;
    float* C        = (z == 0) ? C0  : (z == 1) ? C1  : C2;
    const int i0 = blockIdx.y * 128;
    const int m0 = blockIdx.x * 128;

    float acc[2][8][4];
    #pragma unroll
    for (int ma = 0; ma < 2; ++ma)
        #pragma unroll
        for (int na = 0; na < 8; ++na)
            #pragma unroll
            for (int c = 0; c < 4; ++c) acc[ma][na][c] = 0.f;

    // staging: 256 threads x 4 cp.async(16B) per chunk (one per tile)
    const int srow  = tid >> 1;        // 0..127
    const int shalf = tid & 1;         // 0 or 1 (u32 cols 0..3 / 4..7)
    const uint32_t s_off4 = (srow * TILE_W + shalf * 4) * 4;   // bytes, 16B-aligned
    const uint32_t smem_b = smem_u32(sm);
    // gmem rows are 512 u32 = 128 uint4; chunk c covers uint4 cols [2c, 2c+2)
    const uint4* gAh = Ah + (size_t)(i0 + srow) * 128 + shalf;
    const uint4* gAl = Al + (size_t)(i0 + srow) * 128 + shalf;
    const uint4* gBh = Bh + (size_t)(m0 + srow) * 128 + shalf;
    const uint4* gBl = Bl + (size_t)(m0 + srow) * 128 + shalf;

    auto issue = [&](int c, int buf) {
        uint32_t bb = smem_b + buf * BUF_U32 * 4;
        cp16(bb + 0 * TILE_U32 * 4 + s_off4, gAh + 2 * c);
        cp16(bb + 1 * TILE_U32 * 4 + s_off4, gAl + 2 * c);
        cp16(bb + 2 * TILE_U32 * 4 + s_off4, gBh + 2 * c);
        cp16(bb + 3 * TILE_U32 * 4 + s_off4, gBl + 2 * c);
    };

    issue(0, 0); CP_COMMIT();
    issue(1, 1); CP_COMMIT();

    for (int c = 0; c < NCHUNK; ++c) {
        const int buf = c & 1;
        if (c + 1 < NCHUNK) { CP_WAIT1(); } else { CP_WAIT0(); }
        __syncthreads();

        const uint32_t* tAh = sm + buf * BUF_U32 + 0 * TILE_U32;
        const uint32_t* tAl = sm + buf * BUF_U32 + 1 * TILE_U32;
        const uint32_t* tBh = sm + buf * BUF_U32 + 2 * TILE_U32;
        const uint32_t* tBl = sm + buf * BUF_U32 + 3 * TILE_U32;

        uint32_t bh[8][2], bl[8][2];
        #pragma unroll
        for (int na = 0; na < 8; ++na) {
            int n = wn + na * 8 + gid;
            bh[na][0] = tBh[n * TILE_W + tig]; bh[na][1] = tBh[n * TILE_W + tig + 4];
            bl[na][0] = tBl[n * TILE_W + tig]; bl[na][1] = tBl[n * TILE_W + tig + 4];
        }
        #pragma unroll
        for (int ma = 0; ma < 2; ++ma) {
            int r = wm + ma * 16 + gid;
            uint32_t ah0 = tAh[r * TILE_W + tig],     ah1 = tAh[(r + 8) * TILE_W + tig];
            uint32_t ah2 = tAh[r * TILE_W + tig + 4], ah3 = tAh[(r + 8) * TILE_W + tig + 4];
            uint32_t al0 = tAl[r * TILE_W + tig],     al1 = tAl[(r + 8) * TILE_W + tig];
            uint32_t al2 = tAl[r * TILE_W + tig + 4], al3 = tAl[(r + 8) * TILE_W + tig + 4];
            #pragma unroll
            for (int na = 0; na < 8; ++na) {
                mma_bf16(acc[ma][na], ah0, ah1, ah2, ah3, bh[na][0], bh[na][1]);
                mma_bf16(acc[ma][na], ah0, ah1, ah2, ah3, bl[na][0], bl[na][1]);
                mma_bf16(acc[ma][na], al0, al1, al2, al3, bh[na][0], bh[na][1]);
            }
        }
        __syncthreads();   // all warps done with buf before it is re-staged
        if (c + 2 < NCHUNK) { issue(c + 2, buf); CP_COMMIT(); }
    }

    #pragma unroll
    for (int ma = 0; ma < 2; ++ma) {
        int r = i0 + wm + ma * 16 + gid;
        #pragma unroll
        for (int na = 0; na < 8; ++na) {
            int cbase = m0 + wn + na * 8 + 2 * tig;
            *(float2*)(C + (size_t)r * D_MODEL + cbase)       = make_float2(acc[ma][na][0], acc[ma][na][1]);
            *(float2*)(C + (size_t)(r + 8) * D_MODEL + cbase) = make_float2(acc[ma][na][2], acc[ma][na][3]);
        }
    }
}

// ---------------------------------------------------------------------------
// In-place INTERLEAVED RoPE with NEGATIVE rotation sign, fused Q+K.
// ---------------------------------------------------------------------------
__global__ void rope_neg_kernel(float* __restrict__ Q, float* __restrict__ K)
{
    int idx = blockIdx.x * blockDim.x + threadIdx.x;
    if (idx >= ROWS * NHEADS * (DH/2)) return;
    int j = idx & 31;
    int h = (idx >> 5) & 15;
    int r = idx >> 9;
    int pos = r & (SEQ - 1);
    float inv = powf(10000.0f, -(float)j / 32.0f);
    float ang = (float)pos * inv;
    float c, s;
    sincosf(ang, &c, &s);
    size_t o = (size_t)r * D_MODEL + h * DH + 2 * j;
    {
        float x1 = Q[o], x2 = Q[o+1];
        Q[o]   =  x1 * c + x2 * s;
        Q[o+1] = -x1 * s + x2 * c;
    }
    {
        float x1 = K[o], x2 = K[o+1];
        K[o]   =  x1 * c + x2 * s;
        K[o+1] = -x1 * s + x2 * c;
    }
}

// ---------------------------------------------------------------------------
// Tensor-core causal flash attention, dh=64 (unchanged from R12).
// ---------------------------------------------------------------------------
__global__ void __launch_bounds__(256, 1)
attn_mma(const float* __restrict__ Q, const float* __restrict__ K,
         const float* __restrict__ V, float* __restrict__ O)
{
    __shared__ float Ks[64][68];
    __shared__ float Vs[64][72];

    const int tid  = threadIdx.x;
    const int w    = tid >> 5;
    const int lane = tid & 31;
    const int gid  = lane >> 2;
    const int tig  = lane & 3;
    const int q0   = blockIdx.x * 128;
    const int h    = blockIdx.y, b = blockIdx.z;
    const int qbase = q0 + w * 16;
    const size_t base = (size_t)b * SEQ * D_MODEL + h * DH;

    uint32_t qf[8][4];
    {
        const float* qr0 = Q + base + (size_t)(qbase + gid) * D_MODEL;
        const float* qr1 = Q + base + (size_t)(qbase + gid + 8) * D_MODEL;
        #pragma unroll
        for (int ks = 0; ks < 8; ++ks) {
            int col = ks * 8 + tig;
            qf[ks][0] = f2tf32(qr0[col]);
            qf[ks][1] = f2tf32(qr1[col]);
            qf[ks][2] = f2tf32(qr0[col + 4]);
            qf[ks][3] = f2tf32(qr1[col + 4]);
        }
    }

    float oacc[8][4];
    #pragma unroll
    for (int na = 0; na < 8; ++na)
        #pragma unroll
        for (int c = 0; c < 4; ++c) oacc[na][c] = 0.f;
    float m1 = -1e30f, m2 = -1e30f, l1 = 0.f, l2 = 0.f;

    const int ntiles = q0 / 64 + 2;
    for (int t = 0; t < ntiles; ++t) {
        const int n0 = t * 64;
        __syncthreads();
        #pragma unroll
        for (int it = 0; it < 4; ++it) {
            int e = tid + it * 256;
            int row = e >> 4, c4 = (e & 15) * 4;
            float4 kv = *(const float4*)(K + base + (size_t)(n0 + row) * D_MODEL + c4);
            float4 vv = *(const float4*)(V + base + (size_t)(n0 + row) * D_MODEL + c4);
            kv.x = f2tf32f(kv.x); kv.y = f2tf32f(kv.y);
            kv.z = f2tf32f(kv.z); kv.w = f2tf32f(kv.w);
            vv.x = f2tf32f(vv.x); vv.y = f2tf32f(vv.y);
            vv.z = f2tf32f(vv.z); vv.w = f2tf32f(vv.w);
            *(float4*)&Ks[row][c4] = kv;
            *(float4*)&Vs[row][c4] = vv;
        }
        __syncthreads();

        if (n0 > qbase + 15) continue;

        float sacc[8][4];
        #pragma unroll
        for (int na = 0; na < 8; ++na)
            #pragma unroll
            for (int c = 0; c < 4; ++c) sacc[na][c] = 0.f;
        #pragma unroll
        for (int ks = 0; ks < 8; ++ks) {
            #pragma unroll
            for (int na = 0; na < 8; ++na) {
                uint32_t b0 = __float_as_uint(Ks[na * 8 + gid][ks * 8 + tig]);
                uint32_t b1 = __float_as_uint(Ks[na * 8 + gid][ks * 8 + tig + 4]);
                mma_tf32(sacc[na], qf[ks][0], qf[ks][1], qf[ks][2], qf[ks][3], b0, b1);
            }
        }

        const bool need_mask = (n0 + 63 > qbase);
        const int row1 = qbase + gid, row2 = row1 + 8;
        float mx1 = -1e30f, mx2 = -1e30f;
        #pragma unroll
        for (int na = 0; na < 8; ++na) {
            int col0 = n0 + na * 8 + 2 * tig;
            float s0 = sacc[na][0] * 0.125f;
            float s1 = sacc[na][1] * 0.125f;
            float s2 = sacc[na][2] * 0.125f;
            float s3 = sacc[na][3] * 0.125f;
            if (need_mask) {
                if (col0     > row1) s0 = -1e30f;
                if (col0 + 1 > row1) s1 = -1e30f;
                if (col0     > row2) s2 = -1e30f;
                if (col0 + 1 > row2) s3 = -1e30f;
            }
            sacc[na][0] = s0; sacc[na][1] = s1; sacc[na][2] = s2; sacc[na][3] = s3;
            mx1 = fmaxf(mx1, fmaxf(s0, s1));
            mx2 = fmaxf(mx2, fmaxf(s2, s3));
        }
        mx1 = fmaxf(mx1, __shfl_xor_sync(0xffffffffu, mx1, 1));
        mx1 = fmaxf(mx1, __shfl_xor_sync(0xffffffffu, mx1, 2));
        mx2 = fmaxf(mx2, __shfl_xor_sync(0xffffffffu, mx2, 1));
        mx2 = fmaxf(mx2, __shfl_xor_sync(0xffffffffu, mx2, 2));

        float m1n = fmaxf(m1, mx1), m2n = fmaxf(m2, mx2);
        float a1 = __expf(m1 - m1n), a2 = __expf(m2 - m2n);
        float rs1 = 0.f, rs2 = 0.f;
        #pragma unroll
        for (int na = 0; na < 8; ++na) {
            float p0 = __expf(sacc[na][0] - m1n);
            float p1 = __expf(sacc[na][1] - m1n);
            float p2 = __expf(sacc[na][2] - m2n);
            float p3 = __expf(sacc[na][3] - m2n);
            sacc[na][0] = p0; sacc[na][1] = p1; sacc[na][2] = p2; sacc[na][3] = p3;
            rs1 += p0 + p1; rs2 += p2 + p3;
        }
        rs1 += __shfl_xor_sync(0xffffffffu, rs1, 1);
        rs1 += __shfl_xor_sync(0xffffffffu, rs1, 2);
        rs2 += __shfl_xor_sync(0xffffffffu, rs2, 1);
        rs2 += __shfl_xor_sync(0xffffffffu, rs2, 2);
        l1 = l1 * a1 + rs1;  m1 = m1n;
        l2 = l2 * a2 + rs2;  m2 = m2n;
        #pragma unroll
        for (int na = 0; na < 8; ++na) {
            oacc[na][0] *= a1; oacc[na][1] *= a1;
            oacc[na][2] *= a2; oacc[na][3] *= a2;
        }

        const int src_lo = (gid << 2) + (tig >> 1);
        const int src_hi = src_lo + 2;
        const bool odd = tig & 1;
        #pragma unroll
        for (int kp = 0; kp < 8; ++kp) {
            float v00 = __shfl_sync(0xffffffffu, sacc[kp][0], src_lo);
            float v01 = __shfl_sync(0xffffffffu, sacc[kp][1], src_lo);
            float v10 = __shfl_sync(0xffffffffu, sacc[kp][2], src_lo);
            float v11 = __shfl_sync(0xffffffffu, sacc[kp][3], src_lo);
            float v20 = __shfl_sync(0xffffffffu, sacc[kp][0], src_hi);
            float v21 = __shfl_sync(0xffffffffu, sacc[kp][1], src_hi);
            float v30 = __shfl_sync(0xffffffffu, sacc[kp][2], src_hi);
            float v31 = __shfl_sync(0xffffffffu, sacc[kp][3], src_hi);
            uint32_t pa0 = f2tf32(odd ? v01 : v00);
            uint32_t pa1 = f2tf32(odd ? v11 : v10);
            uint32_t pa2 = f2tf32(odd ? v21 : v20);
            uint32_t pa3 = f2tf32(odd ? v31 : v30);
            #pragma unroll
            for (int na = 0; na < 8; ++na) {
                uint32_t b0 = __float_as_uint(Vs[kp * 8 + tig][na * 8 + gid]);
                uint32_t b1 = __float_as_uint(Vs[kp * 8 + tig + 4][na * 8 + gid]);
                mma_tf32(oacc[na], pa0, pa1, pa2, pa3, b0, b1);
            }
        }
    }

    const float inv1 = 1.0f / l1, inv2 = 1.0f / l2;
    float* o1 = O + base + (size_t)(qbase + gid) * D_MODEL;
    float* o2 = O + base + (size_t)(qbase + gid + 8) * D_MODEL;
    #pragma unroll
    for (int na = 0; na < 8; ++na) {
        int col = na * 8 + 2 * tig;
        *(float2*)(o1 + col) = make_float2(oacc[na][0] * inv1, oacc[na][1] * inv1);
        *(float2*)(o2 + col) = make_float2(oacc[na][2] * inv2, oacc[na][3] * inv2);
    }
}

// ---------------------------------------------------------------------------
extern "C" void kernel_launch(void* const* d_in, const int* in_sizes, int n_in,
                              void* d_out, int out_size)
{
    const float* x  = (const float*)d_in[0];
    const float* Wq = (const float*)d_in[1];
    const float* Wk = (const float*)d_in[2];
    const float* Wv = (const float*)d_in[3];
    const float* Wo = (const float*)d_in[4];
    float* out = (float*)d_out;

    float *qb, *kb, *vb, *ob;
    cudaGetSymbolAddress((void**)&qb, g_Q);
    cudaGetSymbolAddress((void**)&kb, g_K);
    cudaGetSymbolAddress((void**)&vb, g_V);
    cudaGetSymbolAddress((void**)&ob, g_O);
    uint32_t *xh, *xl, *wqh, *wql, *wkh, *wkl, *wvh, *wvl, *woh, *wol, *oh, *ol;
    cudaGetSymbolAddress((void**)&xh,  g_xh);  cudaGetSymbolAddress((void**)&xl,  g_xl);
    cudaGetSymbolAddress((void**)&wqh, g_wqh); cudaGetSymbolAddress((void**)&wql, g_wql);
    cudaGetSymbolAddress((void**)&wkh, g_wkh); cudaGetSymbolAddress((void**)&wkl, g_wkl);
    cudaGetSymbolAddress((void**)&wvh, g_wvh); cudaGetSymbolAddress((void**)&wvl, g_wvl);
    cudaGetSymbolAddress((void**)&woh, g_woh); cudaGetSymbolAddress((void**)&wol, g_wol);
    cudaGetSymbolAddress((void**)&oh,  g_oh);  cudaGetSymbolAddress((void**)&ol,  g_ol);

    cudaFuncSetAttribute(gemm_nt_pre, cudaFuncAttributeMaxDynamicSharedMemorySize, GEMM_SMEM);

    const int n4x = ROWS * D_MODEL / 4;
    const int n4w = D_MODEL * D_MODEL / 4;
    split_bf16<<<n4x/256, 256>>>((const float4*)x,  (uint2*)xh,  (uint2*)xl,  n4x);
    split_bf16<<<n4w/256, 256>>>((const float4*)Wq, (uint2*)wqh, (uint2*)wql, n4w);
    split_bf16<<<n4w/256, 256>>>((const float4*)Wk, (uint2*)wkh, (uint2*)wkl, n4w);
    split_bf16<<<n4w/256, 256>>>((const float4*)Wv, (uint2*)wvh, (uint2*)wvl, n4w);
    split_bf16<<<n4w/256, 256>>>((const float4*)Wo, (uint2*)woh, (uint2*)wol, n4w);

    gemm_nt_pre<<<dim3(D_MODEL/128, ROWS/128, 3), 256, GEMM_SMEM>>>(
        (const uint4*)xh, (const uint4*)xl,
        (const uint4*)wqh, (const uint4*)wql,
        (const uint4*)wkh, (const uint4*)wkl,
        (const uint4*)wvh, (const uint4*)wvl,
        qb, kb, vb);

    int nrope = ROWS * NHEADS * (DH/2);
    rope_neg_kernel<<<(nrope + 255) / 256, 256>>>(qb, kb);

    attn_mma<<<dim3(SEQ/128, NHEADS, BATCH), 256>>>(qb, kb, vb, ob);

    split_bf16<<<n4x/256, 256>>>((const float4*)ob, (uint2*)oh, (uint2*)ol, n4x);
    gemm_nt_pre<<<dim3(D_MODEL/128, ROWS/128, 1), 256, GEMM_SMEM>>>(
        (const uint4*)oh, (const uint4*)ol,
        (const uint4*)woh, (const uint4*)wol,
        (const uint4*)woh, (const uint4*)wol,
        (const uint4*)woh, (const uint4*)wol,
        out, out, out);
}

// round 15
// speedup vs baseline: 3.1793x; 1.0578x over previous
#include <cuda_runtime.h>
#include <math.h>
#include <stdint.h>

#define D_MODEL 1024
#define SEQ     2048
#define BATCH   2
#define NHEADS  16
#define DH      64
#define ROWS    (BATCH*SEQ)   // 4096

// ---------------------------------------------------------------------------
// Scratch (alloc-free: __device__ globals)
// ---------------------------------------------------------------------------
__device__ float g_Q[ROWS*D_MODEL];
__device__ float g_K[ROWS*D_MODEL];
__device__ float g_V[ROWS*D_MODEL];
__device__ float g_O[ROWS*D_MODEL];
// bf16 hi/lo splits, packed as uint32 = bf16x2 (low 16 bits = even-k element)
__device__ uint32_t g_xh[ROWS*D_MODEL/2],     g_xl[ROWS*D_MODEL/2];
__device__ uint32_t g_wqh[D_MODEL*D_MODEL/2], g_wql[D_MODEL*D_MODEL/2];
__device__ uint32_t g_wkh[D_MODEL*D_MODEL/2], g_wkl[D_MODEL*D_MODEL/2];
__device__ uint32_t g_wvh[D_MODEL*D_MODEL/2], g_wvl[D_MODEL*D_MODEL/2];
__device__ uint32_t g_woh[D_MODEL*D_MODEL/2], g_wol[D_MODEL*D_MODEL/2];
__device__ uint32_t g_oh[ROWS*D_MODEL/2],     g_ol[ROWS*D_MODEL/2];

// ---------------------------------------------------------------------------
// Numeric / PTX helpers (legacy mma.sync only — tcgen05 unavailable at the
// harness's compute_103 PTX target)
// ---------------------------------------------------------------------------
__device__ __forceinline__ uint32_t f2tf32(float x) {
    uint32_t r; asm("cvt.rna.tf32.f32 %0, %1;" : "=r"(r) : "f"(x)); return r;
}
__device__ __forceinline__ float f2tf32f(float x) {
    uint32_t r; asm("cvt.rna.tf32.f32 %0, %1;" : "=r"(r) : "f"(x));
    return __uint_as_float(r);
}
__device__ __forceinline__ void mma_tf32(float* d,
                                         uint32_t a0, uint32_t a1, uint32_t a2, uint32_t a3,
                                         uint32_t b0, uint32_t b1) {
    asm volatile(
        "mma.sync.aligned.m16n8k8.row.col.f32.tf32.tf32.f32 "
        "{%0,%1,%2,%3}, {%4,%5,%6,%7}, {%8,%9}, {%0,%1,%2,%3};"
        : "+f"(d[0]), "+f"(d[1]), "+f"(d[2]), "+f"(d[3])
        : "r"(a0), "r"(a1), "r"(a2), "r"(a3), "r"(b0), "r"(b1));
}
__device__ __forceinline__ void mma_bf16(float* d,
                                         uint32_t a0, uint32_t a1, uint32_t a2, uint32_t a3,
                                         uint32_t b0, uint32_t b1) {
    asm volatile(
        "mma.sync.aligned.m16n8k16.row.col.f32.bf16.bf16.f32 "
        "{%0,%1,%2,%3}, {%4,%5,%6,%7}, {%8,%9}, {%0,%1,%2,%3};"
        : "+f"(d[0]), "+f"(d[1]), "+f"(d[2]), "+f"(d[3])
        : "r"(a0), "r"(a1), "r"(a2), "r"(a3), "r"(b0), "r"(b1));
}
__device__ __forceinline__ void split2(float f0, float f1, uint32_t& hi, uint32_t& lo) {
    asm("cvt.rn.bf16x2.f32 %0, %1, %2;" : "=r"(hi) : "f"(f1), "f"(f0));
    float r0 = f0 - __uint_as_float(hi << 16);
    float r1 = f1 - __uint_as_float(hi & 0xFFFF0000u);
    asm("cvt.rn.bf16x2.f32 %0, %1, %2;" : "=r"(lo) : "f"(r1), "f"(r0));
}
__device__ __forceinline__ uint32_t smem_u32(const void* p) {
    uint32_t a;
    asm("{ .reg .u64 t; cvta.to.shared.u64 t, %1; cvt.u32.u64 %0, t; }" : "=r"(a) : "l"(p));
    return a;
}
__device__ __forceinline__ void cp16(uint32_t s, const void* g) {
    asm volatile("cp.async.cg.shared.global [%0], [%1], 16;" :: "r"(s), "l"(g) : "memory");
}
#define CP_COMMIT() asm volatile("cp.async.commit_group;" ::: "memory")
#define CP_WAIT1()  asm volatile("cp.async.wait_group 1;" ::: "memory")
#define CP_WAIT0()  asm volatile("cp.async.wait_group 0;" ::: "memory")

// ---------------------------------------------------------------------------
// Split kernels: float -> bf16 hi/lo packed pairs.
// ---------------------------------------------------------------------------
__global__ void split_bf16(const float4* __restrict__ in, uint2* __restrict__ hi,
                           uint2* __restrict__ lo, int n4)
{
    int i = blockIdx.x * blockDim.x + threadIdx.x;
    if (i >= n4) return;
    float4 v = in[i];
    uint32_t h0, l0, h1, l1;
    split2(v.x, v.y, h0, l0);
    split2(v.z, v.w, h1, l1);
    hi[i] = make_uint2(h0, h1);
    lo[i] = make_uint2(l0, l1);
}
// All 4 weights in one launch (grid.z selects the matrix).
__global__ void split_bf16_w4(const float4* __restrict__ w0, const float4* __restrict__ w1,
                              const float4* __restrict__ w2, const float4* __restrict__ w3,
                              uint2* __restrict__ h0p, uint2* __restrict__ l0p,
                              uint2* __restrict__ h1p, uint2* __restrict__ l1p,
                              uint2* __restrict__ h2p, uint2* __restrict__ l2p,
                              uint2* __restrict__ h3p, uint2* __restrict__ l3p,
                              int n4)
{
    int i = blockIdx.x * blockDim.x + threadIdx.x;
    if (i >= n4) return;
    int z = blockIdx.z;
    const float4* in = (z == 0) ? w0 : (z == 1) ? w1 : (z == 2) ? w2 : w3;
    uint2* hi = (z == 0) ? h0p : (z == 1) ? h1p : (z == 2) ? h2p : h3p;
    uint2* lo = (z == 0) ? l0p : (z == 1) ? l1p : (z == 2) ? l2p : l3p;
    float4 v = in[i];
    uint32_t a0, b0, a1, b1;
    split2(v.x, v.y, a0, b0);
    split2(v.z, v.w, a1, b1);
    hi[i] = make_uint2(a0, a1);
    lo[i] = make_uint2(b0, b1);
}

// ---------------------------------------------------------------------------
// GEMM (unchanged from R14): pre-split bf16 hi/lo, 128x128 tile, cp.async
// double-buffered, 3-term bf16 scheme, occ 2.
// ---------------------------------------------------------------------------
#define TILE_W    12
#define TILE_U32  (128*TILE_W)
#define BUF_U32   (4*TILE_U32)
#define GEMM_SMEM (2*BUF_U32*4)       // 49152 B
#define NCHUNK    64

__global__ void __launch_bounds__(256, 2)
gemm_nt_pre(const uint4* __restrict__ Ah, const uint4* __restrict__ Al,
            const uint4* __restrict__ Bh0, const uint4* __restrict__ Bl0,
            const uint4* __restrict__ Bh1, const uint4* __restrict__ Bl1,
            const uint4* __restrict__ Bh2, const uint4* __restrict__ Bl2,
            float* __restrict__ C0, float* __restrict__ C1, float* __restrict__ C2)
{
    extern __shared__ uint32_t sm[];
    const int tid  = threadIdx.x;
    const int wid  = tid >> 5;
    const int lane = tid & 31;
    const int gid  = lane >> 2;
    const int tig  = lane & 3;
    const int wm   = (wid & 3) * 32;
    const int wn   = (wid >> 2) * 64;
    const int z    = blockIdx.z;
    const uint4* Bh = (z == 0) ? Bh0 : (z == 1) ? Bh1 : Bh2;
    const uint4* Bl = (z == 0) ? Bl0 : (z == 1) ? Bl1 : Bl2;
    float* C        = (z == 0) ? C0  : (z == 1) ? C1  : C2;
    const int i0 = blockIdx.y * 128;
    const int m0 = blockIdx.x * 128;

    float acc[2][8][4];
    #pragma unroll
    for (int ma = 0; ma < 2; ++ma)
        #pragma unroll
        for (int na = 0; na < 8; ++na)
            #pragma unroll
            for (int c = 0; c < 4; ++c) acc[ma][na][c] = 0.f;

    const int srow  = tid >> 1;
    const int shalf = tid & 1;
    const uint32_t s_off4 = (srow * TILE_W + shalf * 4) * 4;
    const uint32_t smem_b = smem_u32(sm);
    const uint4* gAh = Ah + (size_t)(i0 + srow) * 128 + shalf;
    const uint4* gAl = Al + (size_t)(i0 + srow) * 128 + shalf;
    const uint4* gBh = Bh + (size_t)(m0 + srow) * 128 + shalf;
    const uint4* gBl = Bl + (size_t)(m0 + srow) * 128 + shalf;

    auto issue = [&](int c, int buf) {
        uint32_t bb = smem_b + buf * BUF_U32 * 4;
        cp16(bb + 0 * TILE_U32 * 4 + s_off4, gAh + 2 * c);
        cp16(bb + 1 * TILE_U32 * 4 + s_off4, gAl + 2 * c);
        cp16(bb + 2 * TILE_U32 * 4 + s_off4, gBh + 2 * c);
        cp16(bb + 3 * TILE_U32 * 4 + s_off4, gBl + 2 * c);
    };

    issue(0, 0); CP_COMMIT();
    issue(1, 1); CP_COMMIT();

    for (int c = 0; c < NCHUNK; ++c) {
        const int buf = c & 1;
        if (c + 1 < NCHUNK) { CP_WAIT1(); } else { CP_WAIT0(); }
        __syncthreads();

        const uint32_t* tAh = sm + buf * BUF_U32 + 0 * TILE_U32;
        const uint32_t* tAl = sm + buf * BUF_U32 + 1 * TILE_U32;
        const uint32_t* tBh = sm + buf * BUF_U32 + 2 * TILE_U32;
        const uint32_t* tBl = sm + buf * BUF_U32 + 3 * TILE_U32;

        uint32_t bh[8][2], bl[8][2];
        #pragma unroll
        for (int na = 0; na < 8; ++na) {
            int n = wn + na * 8 + gid;
            bh[na][0] = tBh[n * TILE_W + tig]; bh[na][1] = tBh[n * TILE_W + tig + 4];
            bl[na][0] = tBl[n * TILE_W + tig]; bl[na][1] = tBl[n * TILE_W + tig + 4];
        }
        #pragma unroll
        for (int ma = 0; ma < 2; ++ma) {
            int r = wm + ma * 16 + gid;
            uint32_t ah0 = tAh[r * TILE_W + tig],     ah1 = tAh[(r + 8) * TILE_W + tig];
            uint32_t ah2 = tAh[r * TILE_W + tig + 4], ah3 = tAh[(r + 8) * TILE_W + tig + 4];
            uint32_t al0 = tAl[r * TILE_W + tig],     al1 = tAl[(r + 8) * TILE_W + tig];
            uint32_t al2 = tAl[r * TILE_W + tig + 4], al3 = tAl[(r + 8) * TILE_W + tig + 4];
            #pragma unroll
            for (int na = 0; na < 8; ++na) {
                mma_bf16(acc[ma][na], ah0, ah1, ah2, ah3, bh[na][0], bh[na][1]);
                mma_bf16(acc[ma][na], ah0, ah1, ah2, ah3, bl[na][0], bl[na][1]);
                mma_bf16(acc[ma][na], al0, al1, al2, al3, bh[na][0], bh[na][1]);
            }
        }
        __syncthreads();
        if (c + 2 < NCHUNK) { issue(c + 2, buf); CP_COMMIT(); }
    }

    #pragma unroll
    for (int ma = 0; ma < 2; ++ma) {
        int r = i0 + wm + ma * 16 + gid;
        #pragma unroll
        for (int na = 0; na < 8; ++na) {
            int cbase = m0 + wn + na * 8 + 2 * tig;
            *(float2*)(C + (size_t)r * D_MODEL + cbase)       = make_float2(acc[ma][na][0], acc[ma][na][1]);
            *(float2*)(C + (size_t)(r + 8) * D_MODEL + cbase) = make_float2(acc[ma][na][2], acc[ma][na][3]);
        }
    }
}

// ---------------------------------------------------------------------------
// In-place INTERLEAVED RoPE with NEGATIVE rotation sign, fused Q+K.
// ---------------------------------------------------------------------------
__global__ void rope_neg_kernel(float* __restrict__ Q, float* __restrict__ K)
{
    int idx = blockIdx.x * blockDim.x + threadIdx.x;
    if (idx >= ROWS * NHEADS * (DH/2)) return;
    int j = idx & 31;
    int h = (idx >> 5) & 15;
    int r = idx >> 9;
    int pos = r & (SEQ - 1);
    float inv = powf(10000.0f, -(float)j / 32.0f);
    float ang = (float)pos * inv;
    float c, s;
    sincosf(ang, &c, &s);
    size_t o = (size_t)r * D_MODEL + h * DH + 2 * j;
    {
        float x1 = Q[o], x2 = Q[o+1];
        Q[o]   =  x1 * c + x2 * s;
        Q[o+1] = -x1 * s + x2 * c;
    }
    {
        float x1 = K[o], x2 = K[o+1];
        K[o]   =  x1 * c + x2 * s;
        K[o+1] = -x1 * s + x2 * c;
    }
}

// ---------------------------------------------------------------------------
// Tensor-core causal flash attention, dh=64, BALANCED PAIRED SCHEDULING.
// grid.x = 8: CTA bx processes q-tiles {bx, 15-bx} (128 rows each)
// sequentially -> constant 19 key-tiles of work per CTA, 256 CTAs total.
// __launch_bounds__(256, 2) for occupancy 2. Numerics identical to R12/R14.
// ---------------------------------------------------------------------------
__global__ void __launch_bounds__(256, 2)
attn_mma(const float* __restrict__ Q, const float* __restrict__ K,
         const float* __restrict__ V, float* __restrict__ O)
{
    __shared__ float Ks[64][68];
    __shared__ float Vs[64][72];

    const int tid  = threadIdx.x;
    const int w    = tid >> 5;
    const int lane = tid & 31;
    const int gid  = lane >> 2;
    const int tig  = lane & 3;
    const int bx   = blockIdx.x;          // 0..7
    const int h    = blockIdx.y, b = blockIdx.z;
    const size_t base = (size_t)b * SEQ * D_MODEL + h * DH;

    for (int chunk = 0; chunk < 2; ++chunk) {
        const int qt = chunk ? (15 - bx) : bx;   // q-tile index 0..15
        const int q0 = qt * 128;
        const int qbase = q0 + w * 16;

        // Q fragments (tf32) for this chunk
        uint32_t qf[8][4];
        {
            const float* qr0 = Q + base + (size_t)(qbase + gid) * D_MODEL;
            const float* qr1 = Q + base + (size_t)(qbase + gid + 8) * D_MODEL;
            #pragma unroll
            for (int ks = 0; ks < 8; ++ks) {
                int col = ks * 8 + tig;
                qf[ks][0] = f2tf32(qr0[col]);
                qf[ks][1] = f2tf32(qr1[col]);
                qf[ks][2] = f2tf32(qr0[col + 4]);
                qf[ks][3] = f2tf32(qr1[col + 4]);
            }
        }

        float oacc[8][4];
        #pragma unroll
        for (int na = 0; na < 8; ++na)
            #pragma unroll
            for (int c = 0; c < 4; ++c) oacc[na][c] = 0.f;
        float m1 = -1e30f, m2 = -1e30f, l1 = 0.f, l2 = 0.f;

        const int ntiles = q0 / 64 + 2;
        for (int t = 0; t < ntiles; ++t) {
            const int n0 = t * 64;
            __syncthreads();
            #pragma unroll
            for (int it = 0; it < 4; ++it) {
                int e = tid + it * 256;
                int row = e >> 4, c4 = (e & 15) * 4;
                float4 kv = *(const float4*)(K + base + (size_t)(n0 + row) * D_MODEL + c4);
                float4 vv = *(const float4*)(V + base + (size_t)(n0 + row) * D_MODEL + c4);
                kv.x = f2tf32f(kv.x); kv.y = f2tf32f(kv.y);
                kv.z = f2tf32f(kv.z); kv.w = f2tf32f(kv.w);
                vv.x = f2tf32f(vv.x); vv.y = f2tf32f(vv.y);
                vv.z = f2tf32f(vv.z); vv.w = f2tf32f(vv.w);
                *(float4*)&Ks[row][c4] = kv;
                *(float4*)&Vs[row][c4] = vv;
            }
            __syncthreads();

            if (n0 > qbase + 15) continue;

            float sacc[8][4];
            #pragma unroll
            for (int na = 0; na < 8; ++na)
                #pragma unroll
                for (int c = 0; c < 4; ++c) sacc[na][c] = 0.f;
            #pragma unroll
            for (int ks = 0; ks < 8; ++ks) {
                #pragma unroll
                for (int na = 0; na < 8; ++na) {
                    uint32_t b0 = __float_as_uint(Ks[na * 8 + gid][ks * 8 + tig]);
                    uint32_t b1 = __float_as_uint(Ks[na * 8 + gid][ks * 8 + tig + 4]);
                    mma_tf32(sacc[na], qf[ks][0], qf[ks][1], qf[ks][2], qf[ks][3], b0, b1);
                }
            }

            const bool need_mask = (n0 + 63 > qbase);
            const int row1 = qbase + gid, row2 = row1 + 8;
            float mx1 = -1e30f, mx2 = -1e30f;
            #pragma unroll
            for (int na = 0; na < 8; ++na) {
                int col0 = n0 + na * 8 + 2 * tig;
                float s0 = sacc[na][0] * 0.125f;
                float s1 = sacc[na][1] * 0.125f;
                float s2 = sacc[na][2] * 0.125f;
                float s3 = sacc[na][3] * 0.125f;
                if (need_mask) {
                    if (col0     > row1) s0 = -1e30f;
                    if (col0 + 1 > row1) s1 = -1e30f;
                    if (col0     > row2) s2 = -1e30f;
                    if (col0 + 1 > row2) s3 = -1e30f;
                }
                sacc[na][0] = s0; sacc[na][1] = s1; sacc[na][2] = s2; sacc[na][3] = s3;
                mx1 = fmaxf(mx1, fmaxf(s0, s1));
                mx2 = fmaxf(mx2, fmaxf(s2, s3));
            }
            mx1 = fmaxf(mx1, __shfl_xor_sync(0xffffffffu, mx1, 1));
            mx1 = fmaxf(mx1, __shfl_xor_sync(0xffffffffu, mx1, 2));
            mx2 = fmaxf(mx2, __shfl_xor_sync(0xffffffffu, mx2, 1));
            mx2 = fmaxf(mx2, __shfl_xor_sync(0xffffffffu, mx2, 2));

            float m1n = fmaxf(m1, mx1), m2n = fmaxf(m2, mx2);
            float a1 = __expf(m1 - m1n), a2 = __expf(m2 - m2n);
            float rs1 = 0.f, rs2 = 0.f;
            #pragma unroll
            for (int na = 0; na < 8; ++na) {
                float p0 = __expf(sacc[na][0] - m1n);
                float p1 = __expf(sacc[na][1] - m1n);
                float p2 = __expf(sacc[na][2] - m2n);
                float p3 = __expf(sacc[na][3] - m2n);
                sacc[na][0] = p0; sacc[na][1] = p1; sacc[na][2] = p2; sacc[na][3] = p3;
                rs1 += p0 + p1; rs2 += p2 + p3;
            }
            rs1 += __shfl_xor_sync(0xffffffffu, rs1, 1);
            rs1 += __shfl_xor_sync(0xffffffffu, rs1, 2);
            rs2 += __shfl_xor_sync(0xffffffffu, rs2, 1);
            rs2 += __shfl_xor_sync(0xffffffffu, rs2, 2);
            l1 = l1 * a1 + rs1;  m1 = m1n;
            l2 = l2 * a2 + rs2;  m2 = m2n;
            #pragma unroll
            for (int na = 0; na < 8; ++na) {
                oacc[na][0] *= a1; oacc[na][1] *= a1;
                oacc[na][2] *= a2; oacc[na][3] *= a2;
            }

            const int src_lo = (gid << 2) + (tig >> 1);
            const int src_hi = src_lo + 2;
            const bool odd = tig & 1;
            #pragma unroll
            for (int kp = 0; kp < 8; ++kp) {
                float v00 = __shfl_sync(0xffffffffu, sacc[kp][0], src_lo);
                float v01 = __shfl_sync(0xffffffffu, sacc[kp][1], src_lo);
                float v10 = __shfl_sync(0xffffffffu, sacc[kp][2], src_lo);
                float v11 = __shfl_sync(0xffffffffu, sacc[kp][3], src_lo);
                float v20 = __shfl_sync(0xffffffffu, sacc[kp][0], src_hi);
                float v21 = __shfl_sync(0xffffffffu, sacc[kp][1], src_hi);
                float v30 = __shfl_sync(0xffffffffu, sacc[kp][2], src_hi);
                float v31 = __shfl_sync(0xffffffffu, sacc[kp][3], src_hi);
                uint32_t pa0 = f2tf32(odd ? v01 : v00);
                uint32_t pa1 = f2tf32(odd ? v11 : v10);
                uint32_t pa2 = f2tf32(odd ? v21 : v20);
                uint32_t pa3 = f2tf32(odd ? v31 : v30);
                #pragma unroll
                for (int na = 0; na < 8; ++na) {
                    uint32_t b0 = __float_as_uint(Vs[kp * 8 + tig][na * 8 + gid]);
                    uint32_t b1 = __float_as_uint(Vs[kp * 8 + tig + 4][na * 8 + gid]);
                    mma_tf32(oacc[na], pa0, pa1, pa2, pa3, b0, b1);
                }
            }
        }

        const float inv1 = 1.0f / l1, inv2 = 1.0f / l2;
        float* o1 = O + base + (size_t)(qbase + gid) * D_MODEL;
        float* o2 = O + base + (size_t)(qbase + gid + 8) * D_MODEL;
        #pragma unroll
        for (int na = 0; na < 8; ++na) {
            int col = na * 8 + 2 * tig;
            *(float2*)(o1 + col) = make_float2(oacc[na][0] * inv1, oacc[na][1] * inv1);
            *(float2*)(o2 + col) = make_float2(oacc[na][2] * inv2, oacc[na][3] * inv2);
        }
    }
}

// ---------------------------------------------------------------------------
extern "C" void kernel_launch(void* const* d_in, const int* in_sizes, int n_in,
                              void* d_out, int out_size)
{
    const float* x  = (const float*)d_in[0];
    const float* Wq = (const float*)d_in[1];
    const float* Wk = (const float*)d_in[2];
    const float* Wv = (const float*)d_in[3];
    const float* Wo = (const float*)d_in[4];
    float* out = (float*)d_out;

    float *qb, *kb, *vb, *ob;
    cudaGetSymbolAddress((void**)&qb, g_Q);
    cudaGetSymbolAddress((void**)&kb, g_K);
    cudaGetSymbolAddress((void**)&vb, g_V);
    cudaGetSymbolAddress((void**)&ob, g_O);
    uint32_t *xh, *xl, *wqh, *wql, *wkh, *wkl, *wvh, *wvl, *woh, *wol, *oh, *ol;
    cudaGetSymbolAddress((void**)&xh,  g_xh);  cudaGetSymbolAddress((void**)&xl,  g_xl);
    cudaGetSymbolAddress((void**)&wqh, g_wqh); cudaGetSymbolAddress((void**)&wql, g_wql);
    cudaGetSymbolAddress((void**)&wkh, g_wkh); cudaGetSymbolAddress((void**)&wkl, g_wkl);
    cudaGetSymbolAddress((void**)&wvh, g_wvh); cudaGetSymbolAddress((void**)&wvl, g_wvl);
    cudaGetSymbolAddress((void**)&woh, g_woh); cudaGetSymbolAddress((void**)&wol, g_wol);
    cudaGetSymbolAddress((void**)&oh,  g_oh);  cudaGetSymbolAddress((void**)&ol,  g_ol);

    cudaFuncSetAttribute(gemm_nt_pre, cudaFuncAttributeMaxDynamicSharedMemorySize, GEMM_SMEM);

    const int n4x = ROWS * D_MODEL / 4;
    const int n4w = D_MODEL * D_MODEL / 4;
    split_bf16<<<n4x/256, 256>>>((const float4*)x, (uint2*)xh, (uint2*)xl, n4x);
    split_bf16_w4<<<dim3(n4w/256, 1, 4), 256>>>(
        (const float4*)Wq, (const float4*)Wk, (const float4*)Wv, (const float4*)Wo,
        (uint2*)wqh, (uint2*)wql, (uint2*)wkh, (uint2*)wkl,
        (uint2*)wvh, (uint2*)wvl, (uint2*)woh, (uint2*)wol, n4w);

    gemm_nt_pre<<<dim3(D_MODEL/128, ROWS/128, 3), 256, GEMM_SMEM>>>(
        (const uint4*)xh, (const uint4*)xl,
        (const uint4*)wqh, (const uint4*)wql,
        (const uint4*)wkh, (const uint4*)wkl,
        (const uint4*)wvh, (const uint4*)wvl,
        qb, kb, vb);

    int nrope = ROWS * NHEADS * (DH/2);
    rope_neg_kernel<<<(nrope + 255) / 256, 256>>>(qb, kb);

    attn_mma<<<dim3(8, NHEADS, BATCH), 256>>>(qb, kb, vb, ob);

    split_bf16<<<n4x/256, 256>>>((const float4*)ob, (uint2*)oh, (uint2*)ol, n4x);
    gemm_nt_pre<<<dim3(D_MODEL/128, ROWS/128, 1), 256, GEMM_SMEM>>>(
        (const uint4*)oh, (const uint4*)ol,
        (const uint4*)woh, (const uint4*)wol,
        (const uint4*)woh, (const uint4*)wol,
        (const uint4*)woh, (const uint4*)wol,
        out, out, out);
}

// round 16
// speedup vs baseline: 3.1955x; 1.0051x over previous
#include <cuda_runtime.h>
#include <math.h>
#include <stdint.h>

#define D_MODEL 1024
#define SEQ     2048
#define BATCH   2
#define NHEADS  16
#define DH      64
#define ROWS    (BATCH*SEQ)   // 4096

// ---------------------------------------------------------------------------
// Scratch (alloc-free: __device__ globals)
// ---------------------------------------------------------------------------
__device__ float g_Q[ROWS*D_MODEL];
__device__ float g_K[ROWS*D_MODEL];
__device__ float g_V[ROWS*D_MODEL];
// bf16 hi/lo splits, packed bf16x2 words, PERMUTED within each k16 group:
// word order per group = [p0,p4,p1,p5,p2,p6,p3,p7] (p = k-pair index).
__device__ uint32_t g_xh[ROWS*D_MODEL/2],     g_xl[ROWS*D_MODEL/2];
__device__ uint32_t g_wqh[D_MODEL*D_MODEL/2], g_wql[D_MODEL*D_MODEL/2];
__device__ uint32_t g_wkh[D_MODEL*D_MODEL/2], g_wkl[D_MODEL*D_MODEL/2];
__device__ uint32_t g_wvh[D_MODEL*D_MODEL/2], g_wvl[D_MODEL*D_MODEL/2];
__device__ uint32_t g_woh[D_MODEL*D_MODEL/2], g_wol[D_MODEL*D_MODEL/2];
__device__ uint32_t g_oh[ROWS*D_MODEL/2],     g_ol[ROWS*D_MODEL/2];

// ---------------------------------------------------------------------------
// Numeric / PTX helpers
// ---------------------------------------------------------------------------
__device__ __forceinline__ uint32_t f2tf32(float x) {
    uint32_t r; asm("cvt.rna.tf32.f32 %0, %1;" : "=r"(r) : "f"(x)); return r;
}
__device__ __forceinline__ float f2tf32f(float x) {
    uint32_t r; asm("cvt.rna.tf32.f32 %0, %1;" : "=r"(r) : "f"(x));
    return __uint_as_float(r);
}
__device__ __forceinline__ void mma_tf32(float* d,
                                         uint32_t a0, uint32_t a1, uint32_t a2, uint32_t a3,
                                         uint32_t b0, uint32_t b1) {
    asm volatile(
        "mma.sync.aligned.m16n8k8.row.col.f32.tf32.tf32.f32 "
        "{%0,%1,%2,%3}, {%4,%5,%6,%7}, {%8,%9}, {%0,%1,%2,%3};"
        : "+f"(d[0]), "+f"(d[1]), "+f"(d[2]), "+f"(d[3])
        : "r"(a0), "r"(a1), "r"(a2), "r"(a3), "r"(b0), "r"(b1));
}
__device__ __forceinline__ void mma_bf16(float* d,
                                         uint32_t a0, uint32_t a1, uint32_t a2, uint32_t a3,
                                         uint32_t b0, uint32_t b1) {
    asm volatile(
        "mma.sync.aligned.m16n8k16.row.col.f32.bf16.bf16.f32 "
        "{%0,%1,%2,%3}, {%4,%5,%6,%7}, {%8,%9}, {%0,%1,%2,%3};"
        : "+f"(d[0]), "+f"(d[1]), "+f"(d[2]), "+f"(d[3])
        : "r"(a0), "r"(a1), "r"(a2), "r"(a3), "r"(b0), "r"(b1));
}
__device__ __forceinline__ void split2(float f0, float f1, uint32_t& hi, uint32_t& lo) {
    asm("cvt.rn.bf16x2.f32 %0, %1, %2;" : "=r"(hi) : "f"(f1), "f"(f0));
    float r0 = f0 - __uint_as_float(hi << 16);
    float r1 = f1 - __uint_as_float(hi & 0xFFFF0000u);
    asm("cvt.rn.bf16x2.f32 %0, %1, %2;" : "=r"(lo) : "f"(r1), "f"(r0));
}
__device__ __forceinline__ uint32_t smem_u32(const void* p) {
    uint32_t a;
    asm("{ .reg .u64 t; cvta.to.shared.u64 t, %1; cvt.u32.u64 %0, t; }" : "=r"(a) : "l"(p));
    return a;
}
__device__ __forceinline__ void cp16(uint32_t s, const void* g) {
    asm volatile("cp.async.cg.shared.global [%0], [%1], 16;" :: "r"(s), "l"(g) : "memory");
}
#define CP_COMMIT() asm volatile("cp.async.commit_group;" ::: "memory")
#define CP_WAIT1()  asm volatile("cp.async.wait_group 1;" ::: "memory")
#define CP_WAIT0()  asm volatile("cp.async.wait_group 0;" ::: "memory")

// ---------------------------------------------------------------------------
// Split kernels: float -> bf16 hi/lo, permuted k16-group layout.
// One thread per k16 group (16 floats): writes 2 uint4 per array.
// ---------------------------------------------------------------------------
__global__ void split_bf16(const float4* __restrict__ in, uint4* __restrict__ hi,
                           uint4* __restrict__ lo, int ngroups)
{
    int i = blockIdx.x * blockDim.x + threadIdx.x;
    if (i >= ngroups) return;
    const float4* g = in + 4 * (size_t)i;
    uint32_t h[8], l[8];
    #pragma unroll
    for (int j = 0; j < 4; ++j) {
        float4 v = g[j];
        split2(v.x, v.y, h[2*j],   l[2*j]);
        split2(v.z, v.w, h[2*j+1], l[2*j+1]);
    }
    hi[2*(size_t)i]     = make_uint4(h[0], h[4], h[1], h[5]);
    hi[2*(size_t)i + 1] = make_uint4(h[2], h[6], h[3], h[7]);
    lo[2*(size_t)i]     = make_uint4(l[0], l[4], l[1], l[5]);
    lo[2*(size_t)i + 1] = make_uint4(l[2], l[6], l[3], l[7]);
}
__global__ void split_bf16_w4(const float4* __restrict__ w0, const float4* __restrict__ w1,
                              const float4* __restrict__ w2, const float4* __restrict__ w3,
                              uint4* __restrict__ h0p, uint4* __restrict__ l0p,
                              uint4* __restrict__ h1p, uint4* __restrict__ l1p,
                              uint4* __restrict__ h2p, uint4* __restrict__ l2p,
                              uint4* __restrict__ h3p, uint4* __restrict__ l3p,
                              int ngroups)
{
    int i = blockIdx.x * blockDim.x + threadIdx.x;
    if (i >= ngroups) return;
    int z = blockIdx.z;
    const float4* in = (z == 0) ? w0 : (z == 1) ? w1 : (z == 2) ? w2 : w3;
    uint4* hi = (z == 0) ? h0p : (z == 1) ? h1p : (z == 2) ? h2p : h3p;
    uint4* lo = (z == 0) ? l0p : (z == 1) ? l1p : (z == 2) ? l2p : l3p;
    const float4* g = in + 4 * (size_t)i;
    uint32_t h[8], l[8];
    #pragma unroll
    for (int j = 0; j < 4; ++j) {
        float4 v = g[j];
        split2(v.x, v.y, h[2*j],   l[2*j]);
        split2(v.z, v.w, h[2*j+1], l[2*j+1]);
    }
    hi[2*(size_t)i]     = make_uint4(h[0], h[4], h[1], h[5]);
    hi[2*(size_t)i + 1] = make_uint4(h[2], h[6], h[3], h[7]);
    lo[2*(size_t)i]     = make_uint4(l[0], l[4], l[1], l[5]);
    lo[2*(size_t)i + 1] = make_uint4(l[2], l[6], l[3], l[7]);
}

// ---------------------------------------------------------------------------
// GEMM: C[i][m] = sum_k A[i][k]*W[m][k] on pre-split permuted bf16 hi/lo.
// Tile 128x128, 256 thr (8 warps: 4m x 2n, warp tile 32x64), BK=32 (2 k16
// sub-steps per barrier window), cp.async double-buffered.
// Fragments load as LDS.64 (uint2) from width-8 rows: bank pairs
// (8*gid+2*tig) all distinct per 16-lane phase -> conflict-free.
// Subtile order per buffer: [g0:Ah,Al,Bh,Bl][g1:Ah,Al,Bh,Bl], 4KB each.
// acc += ah*bh + ah*bl + al*bh  (bitwise identical scheme/order to R15).
// ---------------------------------------------------------------------------
#define SUB_U32   1024                 // 128 rows x 8 u32
#define BUF_U32   (8*SUB_U32)          // 32KB
#define GEMM_SMEM (2*BUF_U32*4)        // 65536 B
#define NCHUNK    32                   // K/32

__global__ void __launch_bounds__(256, 2)
gemm_nt_pre(const uint4* __restrict__ Ah, const uint4* __restrict__ Al,
            const uint4* __restrict__ Bh0, const uint4* __restrict__ Bl0,
            const uint4* __restrict__ Bh1, const uint4* __restrict__ Bl1,
            const uint4* __restrict__ Bh2, const uint4* __restrict__ Bl2,
            float* __restrict__ C0, float* __restrict__ C1, float* __restrict__ C2)
{
    extern __shared__ uint32_t sm[];
    const int tid  = threadIdx.x;
    const int wid  = tid >> 5;
    const int lane = tid & 31;
    const int gid  = lane >> 2;
    const int tig  = lane & 3;
    const int wm   = (wid & 3) * 32;
    const int wn   = (wid >> 2) * 64;
    const int z    = blockIdx.z;
    const uint4* Bh = (z == 0) ? Bh0 : (z == 1) ? Bh1 : Bh2;
    const uint4* Bl = (z == 0) ? Bl0 : (z == 1) ? Bl1 : Bl2;
    float* C        = (z == 0) ? C0  : (z == 1) ? C1  : C2;
    const int i0 = blockIdx.y * 128;
    const int m0 = blockIdx.x * 128;

    float acc[2][8][4];
    #pragma unroll
    for (int ma = 0; ma < 2; ++ma)
        #pragma unroll
        for (int na = 0; na < 8; ++na)
            #pragma unroll
            for (int c = 0; c < 4; ++c) acc[ma][na][c] = 0.f;

    // staging: thread (srow, shalf) copies half `shalf` of both k16 groups
    // for all 4 operands -> 8 cp16 per chunk.
    const int srow  = tid >> 1;        // 0..127
    const int shalf = tid & 1;         // 0 or 1
    const uint32_t smem_b = smem_u32(sm);
    // gmem row stride = 512 u32 = 128 uint4; chunk c -> uint4 cols [4c, 4c+4)
    const uint4* gAh = Ah + (size_t)(i0 + srow) * 128 + shalf;
    const uint4* gAl = Al + (size_t)(i0 + srow) * 128 + shalf;
    const uint4* gBh = Bh + (size_t)(m0 + srow) * 128 + shalf;
    const uint4* gBl = Bl + (size_t)(m0 + srow) * 128 + shalf;

    auto issue = [&](int c, int buf) {
        uint32_t bb = smem_b + buf * (BUF_U32 * 4);
        #pragma unroll
        for (int g = 0; g < 2; ++g) {
            size_t si = (size_t)c * 4 + g * 2;                   // + shalf in ptr
            uint32_t db = bb + g * 16384 + srow * 32 + shalf * 16;
            cp16(db + 0 * 4096, gAh + si);
            cp16(db + 1 * 4096, gAl + si);
            cp16(db + 2 * 4096, gBh + si);
            cp16(db + 3 * 4096, gBl + si);
        }
    };

    issue(0, 0); CP_COMMIT();
    issue(1, 1); CP_COMMIT();

    for (int c = 0; c < NCHUNK; ++c) {
        const int buf = c & 1;
        if (c + 1 < NCHUNK) { CP_WAIT1(); } else { CP_WAIT0(); }
        __syncthreads();

        const uint32_t* bb = sm + buf * BUF_U32;
        #pragma unroll
        for (int ks = 0; ks < 2; ++ks) {
            const uint32_t* tAh = bb + (ks * 4 + 0) * SUB_U32;
            const uint32_t* tAl = bb + (ks * 4 + 1) * SUB_U32;
            const uint32_t* tBh = bb + (ks * 4 + 2) * SUB_U32;
            const uint32_t* tBl = bb + (ks * 4 + 3) * SUB_U32;

            uint2 bh[8], bl[8];
            #pragma unroll
            for (int na = 0; na < 8; ++na) {
                int n = wn + na * 8 + gid;
                bh[na] = *(const uint2*)&tBh[n * 8 + 2 * tig];
                bl[na] = *(const uint2*)&tBl[n * 8 + 2 * tig];
            }
            #pragma unroll
            for (int ma = 0; ma < 2; ++ma) {
                int r = wm + ma * 16 + gid;
                uint2 ahr = *(const uint2*)&tAh[r * 8 + 2 * tig];
                uint2 ahR = *(const uint2*)&tAh[(r + 8) * 8 + 2 * tig];
                uint2 alr = *(const uint2*)&tAl[r * 8 + 2 * tig];
                uint2 alR = *(const uint2*)&tAl[(r + 8) * 8 + 2 * tig];
                #pragma unroll
                for (int na = 0; na < 8; ++na) {
                    mma_bf16(acc[ma][na], ahr.x, ahR.x, ahr.y, ahR.y, bh[na].x, bh[na].y);
                    mma_bf16(acc[ma][na], ahr.x, ahR.x, ahr.y, ahR.y, bl[na].x, bl[na].y);
                    mma_bf16(acc[ma][na], alr.x, alR.x, alr.y, alR.y, bh[na].x, bh[na].y);
                }
            }
        }
        __syncthreads();
        if (c + 2 < NCHUNK) { issue(c + 2, buf); CP_COMMIT(); }
    }

    #pragma unroll
    for (int ma = 0; ma < 2; ++ma) {
        int r = i0 + wm + ma * 16 + gid;
        #pragma unroll
        for (int na = 0; na < 8; ++na) {
            int cbase = m0 + wn + na * 8 + 2 * tig;
            *(float2*)(C + (size_t)r * D_MODEL + cbase)       = make_float2(acc[ma][na][0], acc[ma][na][1]);
            *(float2*)(C + (size_t)(r + 8) * D_MODEL + cbase) = make_float2(acc[ma][na][2], acc[ma][na][3]);
        }
    }
}

// ---------------------------------------------------------------------------
// In-place INTERLEAVED RoPE with NEGATIVE rotation sign, fused Q+K.
// ---------------------------------------------------------------------------
__global__ void rope_neg_kernel(float* __restrict__ Q, float* __restrict__ K)
{
    int idx = blockIdx.x * blockDim.x + threadIdx.x;
    if (idx >= ROWS * NHEADS * (DH/2)) return;
    int j = idx & 31;
    int h = (idx >> 5) & 15;
    int r = idx >> 9;
    int pos = r & (SEQ - 1);
    float inv = powf(10000.0f, -(float)j / 32.0f);
    float ang = (float)pos * inv;
    float c, s;
    sincosf(ang, &c, &s);
    size_t o = (size_t)r * D_MODEL + h * DH + 2 * j;
    {
        float x1 = Q[o], x2 = Q[o+1];
        Q[o]   =  x1 * c + x2 * s;
        Q[o+1] = -x1 * s + x2 * c;
    }
    {
        float x1 = K[o], x2 = K[o+1];
        K[o]   =  x1 * c + x2 * s;
        K[o+1] = -x1 * s + x2 * c;
    }
}

// ---------------------------------------------------------------------------
// Tensor-core causal flash attention, dh=64, balanced paired scheduling
// (unchanged math from R15). Epilogue now writes bf16 hi/lo splits in the
// permuted layout directly (identical values to the old split kernel).
// ---------------------------------------------------------------------------
__global__ void __launch_bounds__(256, 2)
attn_mma(const float* __restrict__ Q, const float* __restrict__ K,
         const float* __restrict__ V,
         uint32_t* __restrict__ OH, uint32_t* __restrict__ OL)
{
    __shared__ float Ks[64][68];
    __shared__ float Vs[64][72];

    const int tid  = threadIdx.x;
    const int w    = tid >> 5;
    const int lane = tid & 31;
    const int gid  = lane >> 2;
    const int tig  = lane & 3;
    const int bx   = blockIdx.x;          // 0..7
    const int h    = blockIdx.y, b = blockIdx.z;
    const size_t base = (size_t)b * SEQ * D_MODEL + h * DH;

    for (int chunk = 0; chunk < 2; ++chunk) {
        const int qt = chunk ? (15 - bx) : bx;
        const int q0 = qt * 128;
        const int qbase = q0 + w * 16;

        uint32_t qf[8][4];
        {
            const float* qr0 = Q + base + (size_t)(qbase + gid) * D_MODEL;
            const float* qr1 = Q + base + (size_t)(qbase + gid + 8) * D_MODEL;
            #pragma unroll
            for (int ks = 0; ks < 8; ++ks) {
                int col = ks * 8 + tig;
                qf[ks][0] = f2tf32(qr0[col]);
                qf[ks][1] = f2tf32(qr1[col]);
                qf[ks][2] = f2tf32(qr0[col + 4]);
                qf[ks][3] = f2tf32(qr1[col + 4]);
            }
        }

        float oacc[8][4];
        #pragma unroll
        for (int na = 0; na < 8; ++na)
            #pragma unroll
            for (int c = 0; c < 4; ++c) oacc[na][c] = 0.f;
        float m1 = -1e30f, m2 = -1e30f, l1 = 0.f, l2 = 0.f;

        const int ntiles = q0 / 64 + 2;
        for (int t = 0; t < ntiles; ++t) {
            const int n0 = t * 64;
            __syncthreads();
            #pragma unroll
            for (int it = 0; it < 4; ++it) {
                int e = tid + it * 256;
                int row = e >> 4, c4 = (e & 15) * 4;
                float4 kv = *(const float4*)(K + base + (size_t)(n0 + row) * D_MODEL + c4);
                float4 vv = *(const float4*)(V + base + (size_t)(n0 + row) * D_MODEL + c4);
                kv.x = f2tf32f(kv.x); kv.y = f2tf32f(kv.y);
                kv.z = f2tf32f(kv.z); kv.w = f2tf32f(kv.w);
                vv.x = f2tf32f(vv.x); vv.y = f2tf32f(vv.y);
                vv.z = f2tf32f(vv.z); vv.w = f2tf32f(vv.w);
                *(float4*)&Ks[row][c4] = kv;
                *(float4*)&Vs[row][c4] = vv;
            }
            __syncthreads();

            if (n0 > qbase + 15) continue;

            float sacc[8][4];
            #pragma unroll
            for (int na = 0; na < 8; ++na)
                #pragma unroll
                for (int c = 0; c < 4; ++c) sacc[na][c] = 0.f;
            #pragma unroll
            for (int ks = 0; ks < 8; ++ks) {
                #pragma unroll
                for (int na = 0; na < 8; ++na) {
                    uint32_t b0 = __float_as_uint(Ks[na * 8 + gid][ks * 8 + tig]);
                    uint32_t b1 = __float_as_uint(Ks[na * 8 + gid][ks * 8 + tig + 4]);
                    mma_tf32(sacc[na], qf[ks][0], qf[ks][1], qf[ks][2], qf[ks][3], b0, b1);
                }
            }

            const bool need_mask = (n0 + 63 > qbase);
            const int row1 = qbase + gid, row2 = row1 + 8;
            float mx1 = -1e30f, mx2 = -1e30f;
            #pragma unroll
            for (int na = 0; na < 8; ++na) {
                int col0 = n0 + na * 8 + 2 * tig;
                float s0 = sacc[na][0] * 0.125f;
                float s1 = sacc[na][1] * 0.125f;
                float s2 = sacc[na][2] * 0.125f;
                float s3 = sacc[na][3] * 0.125f;
                if (need_mask) {
                    if (col0     > row1) s0 = -1e30f;
                    if (col0 + 1 > row1) s1 = -1e30f;
                    if (col0     > row2) s2 = -1e30f;
                    if (col0 + 1 > row2) s3 = -1e30f;
                }
                sacc[na][0] = s0; sacc[na][1] = s1; sacc[na][2] = s2; sacc[na][3] = s3;
                mx1 = fmaxf(mx1, fmaxf(s0, s1));
                mx2 = fmaxf(mx2, fmaxf(s2, s3));
            }
            mx1 = fmaxf(mx1, __shfl_xor_sync(0xffffffffu, mx1, 1));
            mx1 = fmaxf(mx1, __shfl_xor_sync(0xffffffffu, mx1, 2));
            mx2 = fmaxf(mx2, __shfl_xor_sync(0xffffffffu, mx2, 1));
            mx2 = fmaxf(mx2, __shfl_xor_sync(0xffffffffu, mx2, 2));

            float m1n = fmaxf(m1, mx1), m2n = fmaxf(m2, mx2);
            float a1 = __expf(m1 - m1n), a2 = __expf(m2 - m2n);
            float rs1 = 0.f, rs2 = 0.f;
            #pragma unroll
            for (int na = 0; na < 8; ++na) {
                float p0 = __expf(sacc[na][0] - m1n);
                float p1 = __expf(sacc[na][1] - m1n);
                float p2 = __expf(sacc[na][2] - m2n);
                float p3 = __expf(sacc[na][3] - m2n);
                sacc[na][0] = p0; sacc[na][1] = p1; sacc[na][2] = p2; sacc[na][3] = p3;
                rs1 += p0 + p1; rs2 += p2 + p3;
            }
            rs1 += __shfl_xor_sync(0xffffffffu, rs1, 1);
            rs1 += __shfl_xor_sync(0xffffffffu, rs1, 2);
            rs2 += __shfl_xor_sync(0xffffffffu, rs2, 1);
            rs2 += __shfl_xor_sync(0xffffffffu, rs2, 2);
            l1 = l1 * a1 + rs1;  m1 = m1n;
            l2 = l2 * a2 + rs2;  m2 = m2n;
            #pragma unroll
            for (int na = 0; na < 8; ++na) {
                oacc[na][0] *= a1; oacc[na][1] *= a1;
                oacc[na][2] *= a2; oacc[na][3] *= a2;
            }

            const int src_lo = (gid << 2) + (tig >> 1);
            const int src_hi = src_lo + 2;
            const bool odd = tig & 1;
            #pragma unroll
            for (int kp = 0; kp < 8; ++kp) {
                float v00 = __shfl_sync(0xffffffffu, sacc[kp][0], src_lo);
                float v01 = __shfl_sync(0xffffffffu, sacc[kp][1], src_lo);
                float v10 = __shfl_sync(0xffffffffu, sacc[kp][2], src_lo);
                float v11 = __shfl_sync(0xffffffffu, sacc[kp][3], src_lo);
                float v20 = __shfl_sync(0xffffffffu, sacc[kp][0], src_hi);
                float v21 = __shfl_sync(0xffffffffu, sacc[kp][1], src_hi);
                float v30 = __shfl_sync(0xffffffffu, sacc[kp][2], src_hi);
                float v31 = __shfl_sync(0xffffffffu, sacc[kp][3], src_hi);
                uint32_t pa0 = f2tf32(odd ? v01 : v00);
                uint32_t pa1 = f2tf32(odd ? v11 : v10);
                uint32_t pa2 = f2tf32(odd ? v21 : v20);
                uint32_t pa3 = f2tf32(odd ? v31 : v30);
                #pragma unroll
                for (int na = 0; na < 8; ++na) {
                    uint32_t b0 = __float_as_uint(Vs[kp * 8 + tig][na * 8 + gid]);
                    uint32_t b1 = __float_as_uint(Vs[kp * 8 + tig + 4][na * 8 + gid]);
                    mma_tf32(oacc[na], pa0, pa1, pa2, pa3, b0, b1);
                }
            }
        }

        // Epilogue: normalize, split to bf16 hi/lo, write permuted layout.
        const float inv1 = 1.0f / l1, inv2 = 1.0f / l2;
        const size_t base_u = (size_t)b * SEQ * 512 + h * 32;
        const int row1 = qbase + gid, row2 = row1 + 8;
        #pragma unroll
        for (int na = 0; na < 8; ++na) {
            int p  = na * 4 + tig;              // pair index within head
            int g  = p >> 3, pp = p & 7;
            int ps = (pp < 4) ? 2 * pp : 2 * (pp - 4) + 1;
            size_t idx = base_u + g * 8 + ps;   // + row*512
            uint32_t hv, lv;
            split2(oacc[na][0] * inv1, oacc[na][1] * inv1, hv, lv);
            OH[idx + (size_t)row1 * 512] = hv;
            OL[idx + (size_t)row1 * 512] = lv;
            split2(oacc[na][2] * inv2, oacc[na][3] * inv2, hv, lv);
            OH[idx + (size_t)row2 * 512] = hv;
            OL[idx + (size_t)row2 * 512] = lv;
        }
    }
}

// ---------------------------------------------------------------------------
extern "C" void kernel_launch(void* const* d_in, const int* in_sizes, int n_in,
                              void* d_out, int out_size)
{
    const float* x  = (const float*)d_in[0];
    const float* Wq = (const float*)d_in[1];
    const float* Wk = (const float*)d_in[2];
    const float* Wv = (const float*)d_in[3];
    const float* Wo = (const float*)d_in[4];
    float* out = (float*)d_out;

    float *qb, *kb, *vb;
    cudaGetSymbolAddress((void**)&qb, g_Q);
    cudaGetSymbolAddress((void**)&kb, g_K);
    cudaGetSymbolAddress((void**)&vb, g_V);
    uint32_t *xh, *xl, *wqh, *wql, *wkh, *wkl, *wvh, *wvl, *woh, *wol, *oh, *ol;
    cudaGetSymbolAddress((void**)&xh,  g_xh);  cudaGetSymbolAddress((void**)&xl,  g_xl);
    cudaGetSymbolAddress((void**)&wqh, g_wqh); cudaGetSymbolAddress((void**)&wql, g_wql);
    cudaGetSymbolAddress((void**)&wkh, g_wkh); cudaGetSymbolAddress((void**)&wkl, g_wkl);
    cudaGetSymbolAddress((void**)&wvh, g_wvh); cudaGetSymbolAddress((void**)&wvl, g_wvl);
    cudaGetSymbolAddress((void**)&woh, g_woh); cudaGetSymbolAddress((void**)&wol, g_wol);
    cudaGetSymbolAddress((void**)&oh,  g_oh);  cudaGetSymbolAddress((void**)&ol,  g_ol);

    cudaFuncSetAttribute(gemm_nt_pre, cudaFuncAttributeMaxDynamicSharedMemorySize, GEMM_SMEM);

    const int ngx = ROWS * D_MODEL / 16;      // 262144 k16 groups
    const int ngw = D_MODEL * D_MODEL / 16;   //  65536
    split_bf16<<<ngx/256, 256>>>((const float4*)x, (uint4*)xh, (uint4*)xl, ngx);
    split_bf16_w4<<<dim3(ngw/256, 1, 4), 256>>>(
        (const float4*)Wq, (const float4*)Wk, (const float4*)Wv, (const float4*)Wo,
        (uint4*)wqh, (uint4*)wql, (uint4*)wkh, (uint4*)wkl,
        (uint4*)wvh, (uint4*)wvl, (uint4*)woh, (uint4*)wol, ngw);

    gemm_nt_pre<<<dim3(D_MODEL/128, ROWS/128, 3), 256, GEMM_SMEM>>>(
        (const uint4*)xh, (const uint4*)xl,
        (const uint4*)wqh, (const uint4*)wql,
        (const uint4*)wkh, (const uint4*)wkl,
        (const uint4*)wvh, (const uint4*)wvl,
        qb, kb, vb);

    int nrope = ROWS * NHEADS * (DH/2);
    rope_neg_kernel<<<(nrope + 255) / 256, 256>>>(qb, kb);

    attn_mma<<<dim3(8, NHEADS, BATCH), 256>>>(qb, kb, vb, oh, ol);

    gemm_nt_pre<<<dim3(D_MODEL/128, ROWS/128, 1), 256, GEMM_SMEM>>>(
        (const uint4*)oh, (const uint4*)ol,
        (const uint4*)woh, (const uint4*)wol,
        (const uint4*)woh, (const uint4*)wol,
        (const uint4*)woh, (const uint4*)wol,
        out, out, out);
}

// round 17
// speedup vs baseline: 4.3815x; 1.3711x over previous
#include <cuda_runtime.h>
#include <cuda_fp16.h>
#include <math.h>
#include <stdint.h>

#define D_MODEL 1024
#define SEQ     2048
#define BATCH   2
#define NHEADS  16
#define DH      64
#define ROWS    (BATCH*SEQ)   // 4096

// ---------------------------------------------------------------------------
// Scratch (alloc-free: __device__ globals)
// fp16 hi/lo splits, packed f16x2 words (low 16 bits = even-k element),
// PERMUTED within each k16 group: word order [p0,p4,p1,p5,p2,p6,p3,p7].
// A-side (x, attn-out): hi+lo. Weights: hi only (2-term scheme).
// ---------------------------------------------------------------------------
__device__ float g_Q[ROWS*D_MODEL];
__device__ float g_K[ROWS*D_MODEL];
__device__ float g_V[ROWS*D_MODEL];
__device__ uint32_t g_xh[ROWS*D_MODEL/2],     g_xl[ROWS*D_MODEL/2];
__device__ uint32_t g_wqh[D_MODEL*D_MODEL/2];
__device__ uint32_t g_wkh[D_MODEL*D_MODEL/2];
__device__ uint32_t g_wvh[D_MODEL*D_MODEL/2];
__device__ uint32_t g_woh[D_MODEL*D_MODEL/2];
__device__ uint32_t g_oh[ROWS*D_MODEL/2],     g_ol[ROWS*D_MODEL/2];

// ---------------------------------------------------------------------------
// Numeric / PTX helpers
// ---------------------------------------------------------------------------
__device__ __forceinline__ uint32_t f2tf32(float x) {
    uint32_t r; asm("cvt.rna.tf32.f32 %0, %1;" : "=r"(r) : "f"(x)); return r;
}
__device__ __forceinline__ float f2tf32f(float x) {
    uint32_t r; asm("cvt.rna.tf32.f32 %0, %1;" : "=r"(r) : "f"(x));
    return __uint_as_float(r);
}
__device__ __forceinline__ void mma_tf32(float* d,
                                         uint32_t a0, uint32_t a1, uint32_t a2, uint32_t a3,
                                         uint32_t b0, uint32_t b1) {
    asm volatile(
        "mma.sync.aligned.m16n8k8.row.col.f32.tf32.tf32.f32 "
        "{%0,%1,%2,%3}, {%4,%5,%6,%7}, {%8,%9}, {%0,%1,%2,%3};"
        : "+f"(d[0]), "+f"(d[1]), "+f"(d[2]), "+f"(d[3])
        : "r"(a0), "r"(a1), "r"(a2), "r"(a3), "r"(b0), "r"(b1));
}
__device__ __forceinline__ void mma_f16(float* d,
                                        uint32_t a0, uint32_t a1, uint32_t a2, uint32_t a3,
                                        uint32_t b0, uint32_t b1) {
    asm volatile(
        "mma.sync.aligned.m16n8k16.row.col.f32.f16.f16.f32 "
        "{%0,%1,%2,%3}, {%4,%5,%6,%7}, {%8,%9}, {%0,%1,%2,%3};"
        : "+f"(d[0]), "+f"(d[1]), "+f"(d[2]), "+f"(d[3])
        : "r"(a0), "r"(a1), "r"(a2), "r"(a3), "r"(b0), "r"(b1));
}
// fp16 hi/lo split of two floats, packed f16x2 (f0 in low 16 bits).
__device__ __forceinline__ void split2h(float f0, float f1, uint32_t& hi, uint32_t& lo) {
    __half2 h = __floats2half2_rn(f0, f1);
    float2 bk = __half22float2(h);
    __half2 l = __floats2half2_rn(f0 - bk.x, f1 - bk.y);
    hi = *reinterpret_cast<uint32_t*>(&h);
    lo = *reinterpret_cast<uint32_t*>(&l);
}
// fp16 hi-only (weights)
__device__ __forceinline__ uint32_t pack2h(float f0, float f1) {
    __half2 h = __floats2half2_rn(f0, f1);
    return *reinterpret_cast<uint32_t*>(&h);
}
__device__ __forceinline__ uint32_t smem_u32(const void* p) {
    uint32_t a;
    asm("{ .reg .u64 t; cvta.to.shared.u64 t, %1; cvt.u32.u64 %0, t; }" : "=r"(a) : "l"(p));
    return a;
}
__device__ __forceinline__ void cp16(uint32_t s, const void* g) {
    asm volatile("cp.async.cg.shared.global [%0], [%1], 16;" :: "r"(s), "l"(g) : "memory");
}
#define CP_COMMIT() asm volatile("cp.async.commit_group;" ::: "memory")
#define CP_WAIT1()  asm volatile("cp.async.wait_group 1;" ::: "memory")
#define CP_WAIT0()  asm volatile("cp.async.wait_group 0;" ::: "memory")

// ---------------------------------------------------------------------------
// Split kernels (permuted k16-group layout).
// ---------------------------------------------------------------------------
__global__ void split_f16(const float4* __restrict__ in, uint4* __restrict__ hi,
                          uint4* __restrict__ lo, int ngroups)
{
    int i = blockIdx.x * blockDim.x + threadIdx.x;
    if (i >= ngroups) return;
    const float4* g = in + 4 * (size_t)i;
    uint32_t h[8], l[8];
    #pragma unroll
    for (int j = 0; j < 4; ++j) {
        float4 v = g[j];
        split2h(v.x, v.y, h[2*j],   l[2*j]);
        split2h(v.z, v.w, h[2*j+1], l[2*j+1]);
    }
    hi[2*(size_t)i]     = make_uint4(h[0], h[4], h[1], h[5]);
    hi[2*(size_t)i + 1] = make_uint4(h[2], h[6], h[3], h[7]);
    lo[2*(size_t)i]     = make_uint4(l[0], l[4], l[1], l[5]);
    lo[2*(size_t)i + 1] = make_uint4(l[2], l[6], l[3], l[7]);
}
// Weights: hi only, all 4 in one launch.
__global__ void split_f16h_w4(const float4* __restrict__ w0, const float4* __restrict__ w1,
                              const float4* __restrict__ w2, const float4* __restrict__ w3,
                              uint4* __restrict__ h0p, uint4* __restrict__ h1p,
                              uint4* __restrict__ h2p, uint4* __restrict__ h3p,
                              int ngroups)
{
    int i = blockIdx.x * blockDim.x + threadIdx.x;
    if (i >= ngroups) return;
    int z = blockIdx.z;
    const float4* in = (z == 0) ? w0 : (z == 1) ? w1 : (z == 2) ? w2 : w3;
    uint4* hi = (z == 0) ? h0p : (z == 1) ? h1p : (z == 2) ? h2p : h3p;
    const float4* g = in + 4 * (size_t)i;
    uint32_t h[8];
    #pragma unroll
    for (int j = 0; j < 4; ++j) {
        float4 v = g[j];
        h[2*j]   = pack2h(v.x, v.y);
        h[2*j+1] = pack2h(v.z, v.w);
    }
    hi[2*(size_t)i]     = make_uint4(h[0], h[4], h[1], h[5]);
    hi[2*(size_t)i + 1] = make_uint4(h[2], h[6], h[3], h[7]);
}

// ---------------------------------------------------------------------------
// GEMM: C[i][m] = sum_k A[i][k]*W[m][k], 2-term fp16 scheme:
//   acc += ah*bh + al*bh    (== a*bh exactly; error = a*(W - fp16(W)))
// Tile 128x128, 256 thr (8 warps: 4m x 2n), BK=32, cp.async double-buffered.
// 3 subtiles per k16 group (Ah, Al, Bh), 4KB each; LDS.64 fragments.
// ---------------------------------------------------------------------------
#define SUB_U32   1024                 // 128 rows x 8 u32 = 4KB
#define GRP_U32   (3*SUB_U32)
#define BUF_U32   (2*GRP_U32)          // 24KB
#define GEMM_SMEM (2*BUF_U32*4)        // 49152 B
#define NCHUNK    32                   // K/32

__global__ void __launch_bounds__(256, 2)
gemm_nt_pre(const uint4* __restrict__ Ah, const uint4* __restrict__ Al,
            const uint4* __restrict__ Bh0, const uint4* __restrict__ Bh1,
            const uint4* __restrict__ Bh2,
            float* __restrict__ C0, float* __restrict__ C1, float* __restrict__ C2)
{
    extern __shared__ uint32_t sm[];
    const int tid  = threadIdx.x;
    const int wid  = tid >> 5;
    const int lane = tid & 31;
    const int gid  = lane >> 2;
    const int tig  = lane & 3;
    const int wm   = (wid & 3) * 32;
    const int wn   = (wid >> 2) * 64;
    const int z    = blockIdx.z;
    const uint4* Bh = (z == 0) ? Bh0 : (z == 1) ? Bh1 : Bh2;
    float* C        = (z == 0) ? C0  : (z == 1) ? C1  : C2;
    const int i0 = blockIdx.y * 128;
    const int m0 = blockIdx.x * 128;

    float acc[2][8][4];
    #pragma unroll
    for (int ma = 0; ma < 2; ++ma)
        #pragma unroll
        for (int na = 0; na < 8; ++na)
            #pragma unroll
            for (int c = 0; c < 4; ++c) acc[ma][na][c] = 0.f;

    const int srow  = tid >> 1;        // 0..127
    const int shalf = tid & 1;         // 0 or 1
    const uint32_t smem_b = smem_u32(sm);
    const uint4* gAh = Ah + (size_t)(i0 + srow) * 128 + shalf;
    const uint4* gAl = Al + (size_t)(i0 + srow) * 128 + shalf;
    const uint4* gBh = Bh + (size_t)(m0 + srow) * 128 + shalf;

    auto issue = [&](int c, int buf) {
        uint32_t bb = smem_b + buf * (BUF_U32 * 4);
        #pragma unroll
        for (int g = 0; g < 2; ++g) {
            size_t si = (size_t)c * 4 + g * 2;
            uint32_t db = bb + g * (GRP_U32 * 4) + srow * 32 + shalf * 16;
            cp16(db + 0 * 4096, gAh + si);
            cp16(db + 1 * 4096, gAl + si);
            cp16(db + 2 * 4096, gBh + si);
        }
    };

    issue(0, 0); CP_COMMIT();
    issue(1, 1); CP_COMMIT();

    for (int c = 0; c < NCHUNK; ++c) {
        const int buf = c & 1;
        if (c + 1 < NCHUNK) { CP_WAIT1(); } else { CP_WAIT0(); }
        __syncthreads();

        const uint32_t* bb = sm + buf * BUF_U32;
        #pragma unroll
        for (int ks = 0; ks < 2; ++ks) {
            const uint32_t* tAh = bb + ks * GRP_U32;
            const uint32_t* tAl = tAh + SUB_U32;
            const uint32_t* tBh = tAh + 2 * SUB_U32;

            uint2 bh[8];
            #pragma unroll
            for (int na = 0; na < 8; ++na) {
                int n = wn + na * 8 + gid;
                bh[na] = *(const uint2*)&tBh[n * 8 + 2 * tig];
            }
            #pragma unroll
            for (int ma = 0; ma < 2; ++ma) {
                int r = wm + ma * 16 + gid;
                uint2 ahr = *(const uint2*)&tAh[r * 8 + 2 * tig];
                uint2 ahR = *(const uint2*)&tAh[(r + 8) * 8 + 2 * tig];
                uint2 alr = *(const uint2*)&tAl[r * 8 + 2 * tig];
                uint2 alR = *(const uint2*)&tAl[(r + 8) * 8 + 2 * tig];
                #pragma unroll
                for (int na = 0; na < 8; ++na) {
                    mma_f16(acc[ma][na], ahr.x, ahR.x, ahr.y, ahR.y, bh[na].x, bh[na].y);
                    mma_f16(acc[ma][na], alr.x, alR.x, alr.y, alR.y, bh[na].x, bh[na].y);
                }
            }
        }
        __syncthreads();
        if (c + 2 < NCHUNK) { issue(c + 2, buf); CP_COMMIT(); }
    }

    #pragma unroll
    for (int ma = 0; ma < 2; ++ma) {
        int r = i0 + wm + ma * 16 + gid;
        #pragma unroll
        for (int na = 0; na < 8; ++na) {
            int cbase = m0 + wn + na * 8 + 2 * tig;
            *(float2*)(C + (size_t)r * D_MODEL + cbase)       = make_float2(acc[ma][na][0], acc[ma][na][1]);
            *(float2*)(C + (size_t)(r + 8) * D_MODEL + cbase) = make_float2(acc[ma][na][2], acc[ma][na][3]);
        }
    }
}

// ---------------------------------------------------------------------------
// In-place INTERLEAVED RoPE with NEGATIVE rotation sign, fused Q+K.
// ---------------------------------------------------------------------------
__global__ void rope_neg_kernel(float* __restrict__ Q, float* __restrict__ K)
{
    int idx = blockIdx.x * blockDim.x + threadIdx.x;
    if (idx >= ROWS * NHEADS * (DH/2)) return;
    int j = idx & 31;
    int h = (idx >> 5) & 15;
    int r = idx >> 9;
    int pos = r & (SEQ - 1);
    float inv = powf(10000.0f, -(float)j / 32.0f);
    float ang = (float)pos * inv;
    float c, s;
    sincosf(ang, &c, &s);
    size_t o = (size_t)r * D_MODEL + h * DH + 2 * j;
    {
        float x1 = Q[o], x2 = Q[o+1];
        Q[o]   =  x1 * c + x2 * s;
        Q[o+1] = -x1 * s + x2 * c;
    }
    {
        float x1 = K[o], x2 = K[o+1];
        K[o]   =  x1 * c + x2 * s;
        K[o+1] = -x1 * s + x2 * c;
    }
}

// ---------------------------------------------------------------------------
// Tensor-core causal flash attention, dh=64, balanced paired scheduling
// (math unchanged from R15/R16). Epilogue writes fp16 hi/lo splits in the
// permuted layout.
// ---------------------------------------------------------------------------
__global__ void __launch_bounds__(256, 2)
attn_mma(const float* __restrict__ Q, const float* __restrict__ K,
         const float* __restrict__ V,
         uint32_t* __restrict__ OH, uint32_t* __restrict__ OL)
{
    __shared__ float Ks[64][68];
    __shared__ float Vs[64][72];

    const int tid  = threadIdx.x;
    const int w    = tid >> 5;
    const int lane = tid & 31;
    const int gid  = lane >> 2;
    const int tig  = lane & 3;
    const int bx   = blockIdx.x;          // 0..7
    const int h    = blockIdx.y, b = blockIdx.z;
    const size_t base = (size_t)b * SEQ * D_MODEL + h * DH;

    for (int chunk = 0; chunk < 2; ++chunk) {
        const int qt = chunk ? (15 - bx) : bx;
        const int q0 = qt * 128;
        const int qbase = q0 + w * 16;

        uint32_t qf[8][4];
        {
            const float* qr0 = Q + base + (size_t)(qbase + gid) * D_MODEL;
            const float* qr1 = Q + base + (size_t)(qbase + gid + 8) * D_MODEL;
            #pragma unroll
            for (int ks = 0; ks < 8; ++ks) {
                int col = ks * 8 + tig;
                qf[ks][0] = f2tf32(qr0[col]);
                qf[ks][1] = f2tf32(qr1[col]);
                qf[ks][2] = f2tf32(qr0[col + 4]);
                qf[ks][3] = f2tf32(qr1[col + 4]);
            }
        }

        float oacc[8][4];
        #pragma unroll
        for (int na = 0; na < 8; ++na)
            #pragma unroll
            for (int c = 0; c < 4; ++c) oacc[na][c] = 0.f;
        float m1 = -1e30f, m2 = -1e30f, l1 = 0.f, l2 = 0.f;

        const int ntiles = q0 / 64 + 2;
        for (int t = 0; t < ntiles; ++t) {
            const int n0 = t * 64;
            __syncthreads();
            #pragma unroll
            for (int it = 0; it < 4; ++it) {
                int e = tid + it * 256;
                int row = e >> 4, c4 = (e & 15) * 4;
                float4 kv = *(const float4*)(K + base + (size_t)(n0 + row) * D_MODEL + c4);
                float4 vv = *(const float4*)(V + base + (size_t)(n0 + row) * D_MODEL + c4);
                kv.x = f2tf32f(kv.x); kv.y = f2tf32f(kv.y);
                kv.z = f2tf32f(kv.z); kv.w = f2tf32f(kv.w);
                vv.x = f2tf32f(vv.x); vv.y = f2tf32f(vv.y);
                vv.z = f2tf32f(vv.z); vv.w = f2tf32f(vv.w);
                *(float4*)&Ks[row][c4] = kv;
                *(float4*)&Vs[row][c4] = vv;
            }
            __syncthreads();

            if (n0 > qbase + 15) continue;

            float sacc[8][4];
            #pragma unroll
            for (int na = 0; na < 8; ++na)
                #pragma unroll
                for (int c = 0; c < 4; ++c) sacc[na][c] = 0.f;
            #pragma unroll
            for (int ks = 0; ks < 8; ++ks) {
                #pragma unroll
                for (int na = 0; na < 8; ++na) {
                    uint32_t b0 = __float_as_uint(Ks[na * 8 + gid][ks * 8 + tig]);
                    uint32_t b1 = __float_as_uint(Ks[na * 8 + gid][ks * 8 + tig + 4]);
                    mma_tf32(sacc[na], qf[ks][0], qf[ks][1], qf[ks][2], qf[ks][3], b0, b1);
                }
            }

            const bool need_mask = (n0 + 63 > qbase);
            const int row1 = qbase + gid, row2 = row1 + 8;
            float mx1 = -1e30f, mx2 = -1e30f;
            #pragma unroll
            for (int na = 0; na < 8; ++na) {
                int col0 = n0 + na * 8 + 2 * tig;
                float s0 = sacc[na][0] * 0.125f;
                float s1 = sacc[na][1] * 0.125f;
                float s2 = sacc[na][2] * 0.125f;
                float s3 = sacc[na][3] * 0.125f;
                if (need_mask) {
                    if (col0     > row1) s0 = -1e30f;
                    if (col0 + 1 > row1) s1 = -1e30f;
                    if (col0     > row2) s2 = -1e30f;
                    if (col0 + 1 > row2) s3 = -1e30f;
                }
                sacc[na][0] = s0; sacc[na][1] = s1; sacc[na][2] = s2; sacc[na][3] = s3;
                mx1 = fmaxf(mx1, fmaxf(s0, s1));
                mx2 = fmaxf(mx2, fmaxf(s2, s3));
            }
            mx1 = fmaxf(mx1, __shfl_xor_sync(0xffffffffu, mx1, 1));
            mx1 = fmaxf(mx1, __shfl_xor_sync(0xffffffffu, mx1, 2));
            mx2 = fmaxf(mx2, __shfl_xor_sync(0xffffffffu, mx2, 1));
            mx2 = fmaxf(mx2, __shfl_xor_sync(0xffffffffu, mx2, 2));

            float m1n = fmaxf(m1, mx1), m2n = fmaxf(m2, mx2);
            float a1 = __expf(m1 - m1n), a2 = __expf(m2 - m2n);
            float rs1 = 0.f, rs2 = 0.f;
            #pragma unroll
            for (int na = 0; na < 8; ++na) {
                float p0 = __expf(sacc[na][0] - m1n);
                float p1 = __expf(sacc[na][1] - m1n);
                float p2 = __expf(sacc[na][2] - m2n);
                float p3 = __expf(sacc[na][3] - m2n);
                sacc[na][0] = p0; sacc[na][1] = p1; sacc[na][2] = p2; sacc[na][3] = p3;
                rs1 += p0 + p1; rs2 += p2 + p3;
            }
            rs1 += __shfl_xor_sync(0xffffffffu, rs1, 1);
            rs1 += __shfl_xor_sync(0xffffffffu, rs1, 2);
            rs2 += __shfl_xor_sync(0xffffffffu, rs2, 1);
            rs2 += __shfl_xor_sync(0xffffffffu, rs2, 2);
            l1 = l1 * a1 + rs1;  m1 = m1n;
            l2 = l2 * a2 + rs2;  m2 = m2n;
            #pragma unroll
            for (int na = 0; na < 8; ++na) {
                oacc[na][0] *= a1; oacc[na][1] *= a1;
                oacc[na][2] *= a2; oacc[na][3] *= a2;
            }

            const int src_lo = (gid << 2) + (tig >> 1);
            const int src_hi = src_lo + 2;
            const bool odd = tig & 1;
            #pragma unroll
            for (int kp = 0; kp < 8; ++kp) {
                float v00 = __shfl_sync(0xffffffffu, sacc[kp][0], src_lo);
                float v01 = __shfl_sync(0xffffffffu, sacc[kp][1], src_lo);
                float v10 = __shfl_sync(0xffffffffu, sacc[kp][2], src_lo);
                float v11 = __shfl_sync(0xffffffffu, sacc[kp][3], src_lo);
                float v20 = __shfl_sync(0xffffffffu, sacc[kp][0], src_hi);
                float v21 = __shfl_sync(0xffffffffu, sacc[kp][1], src_hi);
                float v30 = __shfl_sync(0xffffffffu, sacc[kp][2], src_hi);
                float v31 = __shfl_sync(0xffffffffu, sacc[kp][3], src_hi);
                uint32_t pa0 = f2tf32(odd ? v01 : v00);
                uint32_t pa1 = f2tf32(odd ? v11 : v10);
                uint32_t pa2 = f2tf32(odd ? v21 : v20);
                uint32_t pa3 = f2tf32(odd ? v31 : v30);
                #pragma unroll
                for (int na = 0; na < 8; ++na) {
                    uint32_t b0 = __float_as_uint(Vs[kp * 8 + tig][na * 8 + gid]);
                    uint32_t b1 = __float_as_uint(Vs[kp * 8 + tig + 4][na * 8 + gid]);
                    mma_tf32(oacc[na], pa0, pa1, pa2, pa3, b0, b1);
                }
            }
        }

        // Epilogue: normalize, fp16 hi/lo split, permuted layout.
        const float inv1 = 1.0f / l1, inv2 = 1.0f / l2;
        const size_t base_u = (size_t)b * SEQ * 512 + h * 32;
        const int row1 = qbase + gid, row2 = row1 + 8;
        #pragma unroll
        for (int na = 0; na < 8; ++na) {
            int p  = na * 4 + tig;              // pair index within head
            int g  = p >> 3, pp = p & 7;
            int ps = (pp < 4) ? 2 * pp : 2 * (pp - 4) + 1;
            size_t idx = base_u + g * 8 + ps;
            uint32_t hv, lv;
            split2h(oacc[na][0] * inv1, oacc[na][1] * inv1, hv, lv);
            OH[idx + (size_t)row1 * 512] = hv;
            OL[idx + (size_t)row1 * 512] = lv;
            split2h(oacc[na][2] * inv2, oacc[na][3] * inv2, hv, lv);
            OH[idx + (size_t)row2 * 512] = hv;
            OL[idx + (size_t)row2 * 512] = lv;
        }
    }
}

// ---------------------------------------------------------------------------
extern "C" void kernel_launch(void* const* d_in, const int* in_sizes, int n_in,
                              void* d_out, int out_size)
{
    const float* x  = (const float*)d_in[0];
    const float* Wq = (const float*)d_in[1];
    const float* Wk = (const float*)d_in[2];
    const float* Wv = (const float*)d_in[3];
    const float* Wo = (const float*)d_in[4];
    float* out = (float*)d_out;

    float *qb, *kb, *vb;
    cudaGetSymbolAddress((void**)&qb, g_Q);
    cudaGetSymbolAddress((void**)&kb, g_K);
    cudaGetSymbolAddress((void**)&vb, g_V);
    uint32_t *xh, *xl, *wqh, *wkh, *wvh, *woh, *oh, *ol;
    cudaGetSymbolAddress((void**)&xh,  g_xh);  cudaGetSymbolAddress((void**)&xl,  g_xl);
    cudaGetSymbolAddress((void**)&wqh, g_wqh);
    cudaGetSymbolAddress((void**)&wkh, g_wkh);
    cudaGetSymbolAddress((void**)&wvh, g_wvh);
    cudaGetSymbolAddress((void**)&woh, g_woh);
    cudaGetSymbolAddress((void**)&oh,  g_oh);  cudaGetSymbolAddress((void**)&ol,  g_ol);

    cudaFuncSetAttribute(gemm_nt_pre, cudaFuncAttributeMaxDynamicSharedMemorySize, GEMM_SMEM);

    const int ngx = ROWS * D_MODEL / 16;      // 262144 k16 groups
    const int ngw = D_MODEL * D_MODEL / 16;   //  65536
    split_f16<<<ngx/256, 256>>>((const float4*)x, (uint4*)xh, (uint4*)xl, ngx);
    split_f16h_w4<<<dim3(ngw/256, 1, 4), 256>>>(
        (const float4*)Wq, (const float4*)Wk, (const float4*)Wv, (const float4*)Wo,
        (uint4*)wqh, (uint4*)wkh, (uint4*)wvh, (uint4*)woh, ngw);

    gemm_nt_pre<<<dim3(D_MODEL/128, ROWS/128, 3), 256, GEMM_SMEM>>>(
        (const uint4*)xh, (const uint4*)xl,
        (const uint4*)wqh, (const uint4*)wkh, (const uint4*)wvh,
        qb, kb, vb);

    int nrope = ROWS * NHEADS * (DH/2);
    rope_neg_kernel<<<(nrope + 255) / 256, 256>>>(qb, kb);

    attn_mma<<<dim3(8, NHEADS, BATCH), 256>>>(qb, kb, vb, oh, ol);

    gemm_nt_pre<<<dim3(D_MODEL/128, ROWS/128, 1), 256, GEMM_SMEM>>>(
        (const uint4*)oh, (const uint4*)ol,
        (const uint4*)woh, (const uint4*)woh, (const uint4*)woh,
        out, out, out);
}